// round 9
// baseline (speedup 1.0000x reference)
#include <cuda_runtime.h>
#include <cuda_bf16.h>
#include <mma.h>
#include <cstdint>

using namespace nvcuda;

#define NN 50000
#define NNP 50048              // padded to 391*128 for guard-free GEMM stores
#define NE 800000
#define EE (NE + NN)           // edges + self loops = 850000
#define HW 256
#define IN_FEAT 128
#define OUTF 40

// ---------------- scratch (static device globals; no runtime allocation) ----
__device__ float g_h[NNP * HW];      // transformed features  (x @ W)
__device__ float g_feat[NNP * HW];   // layer output / next layer input (pad rows stay 0)
__device__ float g_oscr[NNP * 128];  // final-GEMM scratch (N=40 padded to 128)
__device__ float g_srcl[NN * 4];
__device__ float g_dstl[NN * 4];
__device__ float g_denom[NN * 4];
__device__ float g_coef[EE * 4];
__device__ int   g_src2[EE];
__device__ int   g_dst2[EE];
__device__ int   g_src_sorted[EE];
__device__ int   g_counts[NN];
__device__ int   g_fill[NN];
__device__ int   g_rowptr[NN + 1];
__device__ int   g_bsum[256];
__device__ int   g_is64;

// ---------------- dtype detection (parallel, no serial latency chain) ------
__global__ void k_detect(const void* __restrict__ ei) {
    __shared__ int bad;
    if (threadIdx.x == 0) bad = 0;
    __syncthreads();
    const long long* p = (const long long*)ei;
    long long v = p[threadIdx.x];              // first 512 int64 = 4KB, safe either dtype
    if (v < 0 || v >= (long long)NN) bad = 1;
    __syncthreads();
    if (threadIdx.x == 0) g_is64 = bad ? 0 : 1;
}

// ---------------- CSR build ----------------
__global__ void k_zero_counts(int* counts, int n) {
    int i = blockIdx.x * blockDim.x + threadIdx.x;
    if (i < n) counts[i] = 0;
}

__global__ void k_build_edges(const void* __restrict__ ei,
                              int* __restrict__ src2, int* __restrict__ dst2,
                              int* __restrict__ counts) {
    int e = blockIdx.x * blockDim.x + threadIdx.x;
    if (e >= EE) return;
    int s, d;
    if (e < NE) {
        if (g_is64) {
            const long long* p = (const long long*)ei;
            s = (int)p[e]; d = (int)p[NE + e];
        } else {
            const int* p = (const int*)ei;
            s = p[e]; d = p[NE + e];
        }
        s = min(max(s, 0), NN - 1);
        d = min(max(d, 0), NN - 1);
    } else {
        s = d = e - NE;
    }
    src2[e] = s;
    dst2[e] = d;
    atomicAdd(&counts[d], 1);
}

// ---------------- hierarchical exclusive scan ------------------------------
#define SCAN_B 256
#define SCAN_NB ((NN + SCAN_B - 1) / SCAN_B)   // 196

__global__ void k_blocksum(const int* __restrict__ counts, int* __restrict__ bsum) {
    __shared__ int s[SCAN_B];
    int i = blockIdx.x * SCAN_B + threadIdx.x;
    s[threadIdx.x] = (i < NN) ? counts[i] : 0;
    __syncthreads();
    for (int off = 128; off > 0; off >>= 1) {
        if (threadIdx.x < off) s[threadIdx.x] += s[threadIdx.x + off];
        __syncthreads();
    }
    if (threadIdx.x == 0) bsum[blockIdx.x] = s[0];
}

__global__ void k_scan_top(int* __restrict__ bsum) {
    __shared__ int s[SCAN_B];
    int v = (threadIdx.x < SCAN_NB) ? bsum[threadIdx.x] : 0;
    s[threadIdx.x] = v;
    __syncthreads();
    for (int off = 1; off < SCAN_B; off <<= 1) {
        int t = (threadIdx.x >= off) ? s[threadIdx.x - off] : 0;
        __syncthreads();
        s[threadIdx.x] += t;
        __syncthreads();
    }
    if (threadIdx.x < SCAN_NB) bsum[threadIdx.x] = s[threadIdx.x] - v;
}

__global__ void k_scan_final(const int* __restrict__ counts, const int* __restrict__ bsum,
                             int* __restrict__ rowptr, int* __restrict__ fill) {
    __shared__ int s[SCAN_B];
    int i = blockIdx.x * SCAN_B + threadIdx.x;
    int v = (i < NN) ? counts[i] : 0;
    s[threadIdx.x] = v;
    __syncthreads();
    for (int off = 1; off < SCAN_B; off <<= 1) {
        int t = (threadIdx.x >= off) ? s[threadIdx.x - off] : 0;
        __syncthreads();
        s[threadIdx.x] += t;
        __syncthreads();
    }
    int excl = bsum[blockIdx.x] + s[threadIdx.x] - v;
    if (i < NN) { rowptr[i] = excl; fill[i] = excl; }
    if (i == NN - 1) rowptr[NN] = excl + v;
}

__global__ void k_scatter(const int* __restrict__ src2, const int* __restrict__ dst2,
                          int* __restrict__ fill, int* __restrict__ src_sorted) {
    int e = blockIdx.x * blockDim.x + threadIdx.x;
    if (e >= EE) return;
    int d = dst2[e];
    int p = atomicAdd(&fill[d], 1);
    src_sorted[p] = src2[e];
}

// ---------------- tf32 GEMM v2: C[M,Nc-pad] = A[M,K] @ B[K,N] --------------
// 128x128 block tile, BK=32, 8 warps each 64x32 (4x2 frags of m16n16k8).
// Register-prefetch double buffering; direct fragment stores (C rows padded).
#define GBM 128
#define GBN 128
#define GBK 32
#define APAD 8
#define BPAD 8

__global__ __launch_bounds__(256) void k_gemm2(
    const float* __restrict__ A, const float* __restrict__ B,
    float* __restrict__ C, int M, int N, int K, int ldc)
{
    __shared__ float As[GBM][GBK + APAD];   // 128 x 40
    __shared__ float Bs[GBK][GBN + BPAD];   // 32 x 136

    int tid = threadIdx.x;
    int warp = tid >> 5;
    int wm = warp >> 2;          // 0..1 -> 64-row slab
    int wn = warp & 3;           // 0..3 -> 32-col slab
    int row0 = blockIdx.y * GBM;
    int col0 = blockIdx.x * GBN;

    wmma::fragment<wmma::accumulator, 16, 16, 8, float> acc[4][2];
#pragma unroll
    for (int i = 0; i < 4; i++)
#pragma unroll
        for (int j = 0; j < 2; j++) wmma::fill_fragment(acc[i][j], 0.0f);

    // loader maps: A tile 128x32 = 1024 float4 -> 4/thread; B tile 32x128 same
    float4 ra[4], rb[4];
    const int T = K / GBK;

    auto load_tiles = [&](int k0) {
#pragma unroll
        for (int i = 0; i < 4; i++) {
            int lin = tid + i * 256;
            int r = lin >> 3, c4 = (lin & 7) * 4;
            ra[i] = make_float4(0.f, 0.f, 0.f, 0.f);
            if (row0 + r < M)
                ra[i] = *(const float4*)(A + (size_t)(row0 + r) * K + k0 + c4);
        }
#pragma unroll
        for (int i = 0; i < 4; i++) {
            int lin = tid + i * 256;
            int r = lin >> 5, c4 = (lin & 31) * 4;
            int gc = col0 + c4;
            if (gc + 4 <= N) {
                rb[i] = *(const float4*)(B + (size_t)(k0 + r) * N + gc);
            } else {
                float v[4] = {0.f, 0.f, 0.f, 0.f};
#pragma unroll
                for (int j = 0; j < 4; j++)
                    if (gc + j < N) v[j] = B[(size_t)(k0 + r) * N + gc + j];
                rb[i] = make_float4(v[0], v[1], v[2], v[3]);
            }
        }
    };

    load_tiles(0);

    for (int t = 0; t < T; t++) {
        // store staged regs -> smem with tf32 RNA conversion
#pragma unroll
        for (int i = 0; i < 4; i++) {
            int lin = tid + i * 256;
            int r = lin >> 3, c4 = (lin & 7) * 4;
            As[r][c4 + 0] = wmma::__float_to_tf32(ra[i].x);
            As[r][c4 + 1] = wmma::__float_to_tf32(ra[i].y);
            As[r][c4 + 2] = wmma::__float_to_tf32(ra[i].z);
            As[r][c4 + 3] = wmma::__float_to_tf32(ra[i].w);
        }
#pragma unroll
        for (int i = 0; i < 4; i++) {
            int lin = tid + i * 256;
            int r = lin >> 5, c4 = (lin & 31) * 4;
            Bs[r][c4 + 0] = wmma::__float_to_tf32(rb[i].x);
            Bs[r][c4 + 1] = wmma::__float_to_tf32(rb[i].y);
            Bs[r][c4 + 2] = wmma::__float_to_tf32(rb[i].z);
            Bs[r][c4 + 3] = wmma::__float_to_tf32(rb[i].w);
        }
        __syncthreads();

        if (t + 1 < T) load_tiles((t + 1) * GBK);   // overlap global loads with mma

#pragma unroll
        for (int kk = 0; kk < GBK; kk += 8) {
            wmma::fragment<wmma::matrix_a, 16, 16, 8, wmma::precision::tf32, wmma::row_major> af[4];
            wmma::fragment<wmma::matrix_b, 16, 16, 8, wmma::precision::tf32, wmma::row_major> bf[2];
#pragma unroll
            for (int i = 0; i < 4; i++)
                wmma::load_matrix_sync(af[i], &As[wm * 64 + i * 16][kk], GBK + APAD);
#pragma unroll
            for (int j = 0; j < 2; j++)
                wmma::load_matrix_sync(bf[j], &Bs[kk][wn * 32 + j * 16], GBN + BPAD);
#pragma unroll
            for (int i = 0; i < 4; i++)
#pragma unroll
                for (int j = 0; j < 2; j++)
                    wmma::mma_sync(acc[i][j], af[i], bf[j], acc[i][j]);
        }
        __syncthreads();
    }

    // direct stores — C has padded rows (NNP) and width ldc, no guards needed
#pragma unroll
    for (int i = 0; i < 4; i++)
#pragma unroll
        for (int j = 0; j < 2; j++) {
            int r = row0 + wm * 64 + i * 16;
            int c = col0 + wn * 32 + j * 16;
            wmma::store_matrix_sync(C + (size_t)r * ldc + c, acc[i][j], ldc,
                                    wmma::mem_row_major);
        }
}

// ---------------- elementwise epilogues ----------------
__global__ void k_biasrelu(float* __restrict__ h, const float* __restrict__ bias) {
    int i = blockIdx.x * blockDim.x + threadIdx.x;     // over NN*64 float4
    if (i >= NN * 64) return;
    int c4 = (i & 63) * 4;
    float4 v = ((float4*)h)[i];
    const float4 b = *(const float4*)(bias + c4);
    v.x = fmaxf(v.x + b.x, 0.f); v.y = fmaxf(v.y + b.y, 0.f);
    v.z = fmaxf(v.z + b.z, 0.f); v.w = fmaxf(v.w + b.w, 0.f);
    ((float4*)h)[i] = v;
}

__global__ void k_copyout(const float* __restrict__ scr, const float* __restrict__ bias,
                          float* __restrict__ out) {
    int i = blockIdx.x * blockDim.x + threadIdx.x;     // over NN*OUTF
    if (i >= NN * OUTF) return;
    int r = i / OUTF, c = i - r * OUTF;
    out[i] = scr[(size_t)r * 128 + c] + bias[c];
}

// ---------------- per-node attention logits: warp per node ----------------
__global__ void k_logits(const float* __restrict__ h, const float* __restrict__ a_s,
                         const float* __restrict__ a_d,
                         float* __restrict__ srcl, float* __restrict__ dstl) {
    int warp = (blockIdx.x * blockDim.x + threadIdx.x) >> 5;
    int lane = threadIdx.x & 31;
    if (warp >= NN) return;
    int n = warp;
    const float4* hp = (const float4*)(h + (size_t)n * HW) + lane * 2;
    float4 v0 = hp[0], v1 = hp[1];
    int head = lane >> 3, sub = lane & 7;
    const float4* ap = (const float4*)(a_s + head * 64 + sub * 8);
    const float4* dp = (const float4*)(a_d + head * 64 + sub * 8);
    float4 s0 = ap[0], s1 = ap[1];
    float4 d0 = dp[0], d1 = dp[1];
    float ps = v0.x * s0.x + v0.y * s0.y + v0.z * s0.z + v0.w * s0.w
             + v1.x * s1.x + v1.y * s1.y + v1.z * s1.z + v1.w * s1.w;
    float pd = v0.x * d0.x + v0.y * d0.y + v0.z * d0.z + v0.w * d0.w
             + v1.x * d1.x + v1.y * d1.y + v1.z * d1.z + v1.w * d1.w;
#pragma unroll
    for (int off = 4; off >= 1; off >>= 1) {
        ps += __shfl_down_sync(0xffffffffu, ps, off, 8);
        pd += __shfl_down_sync(0xffffffffu, pd, off, 8);
    }
    if (sub == 0) {
        srcl[n * 4 + head] = ps;
        dstl[n * 4 + head] = pd;
    }
}

// ---------------- segment softmax: one thread per (node, head) -------------
__global__ void k_attn(const float* __restrict__ srcl, const float* __restrict__ dstl,
                       const int* __restrict__ rowptr, const int* __restrict__ src_sorted,
                       float* __restrict__ coef, float* __restrict__ denom) {
    int t = blockIdx.x * blockDim.x + threadIdx.x;
    if (t >= NN * 4) return;
    int n = t >> 2, hd = t & 3;
    float dl = dstl[t];
    int b = rowptr[n], e = rowptr[n + 1];
    float mx = -1e30f;
    for (int i = b; i < e; i++) {
        int s = src_sorted[i];
        float a = srcl[s * 4 + hd] + dl;
        a = a > 0.f ? a : 0.2f * a;
        coef[i * 4 + hd] = a;
        mx = fmaxf(mx, a);
    }
    float sum = 0.f;
    for (int i = b; i < e; i++) {
        float ev = __expf(coef[i * 4 + hd] - mx);
        coef[i * 4 + hd] = ev;
        sum += ev;
    }
    denom[t] = sum;
}

// ---------------- aggregation: warp per destination node, no atomics -------
__global__ void k_agg(const float* __restrict__ h, const int* __restrict__ rowptr,
                      const int* __restrict__ src_sorted, const float* __restrict__ coef,
                      const float* __restrict__ denom, const float* __restrict__ bias,
                      float* __restrict__ out) {
    int warp = (blockIdx.x * blockDim.x + threadIdx.x) >> 5;
    int lane = threadIdx.x & 31;
    if (warp >= NN) return;
    int n = warp;
    int head = lane >> 3;
    float rinv = 1.0f / denom[n * 4 + head];
    int b = rowptr[n], e = rowptr[n + 1];
    float4 a0 = make_float4(0.f, 0.f, 0.f, 0.f);
    float4 a1 = make_float4(0.f, 0.f, 0.f, 0.f);
    for (int i = b; i < e; i++) {
        int s = src_sorted[i];
        float4 cq = ((const float4*)coef)[i];
        float c = (head == 0) ? cq.x : (head == 1) ? cq.y : (head == 2) ? cq.z : cq.w;
        c *= rinv;
        const float4* hp = (const float4*)(h + (size_t)s * HW) + lane * 2;
        float4 v0 = hp[0], v1 = hp[1];
        a0.x += v0.x * c; a0.y += v0.y * c; a0.z += v0.z * c; a0.w += v0.w * c;
        a1.x += v1.x * c; a1.y += v1.y * c; a1.z += v1.z * c; a1.w += v1.w * c;
    }
    const float4* bp = (const float4*)bias + lane * 2;
    float4 b0 = bp[0], b1 = bp[1];
    float4 o0, o1;
    o0.x = fmaxf(a0.x + b0.x, 0.f); o0.y = fmaxf(a0.y + b0.y, 0.f);
    o0.z = fmaxf(a0.z + b0.z, 0.f); o0.w = fmaxf(a0.w + b0.w, 0.f);
    o1.x = fmaxf(a1.x + b1.x, 0.f); o1.y = fmaxf(a1.y + b1.y, 0.f);
    o1.z = fmaxf(a1.z + b1.z, 0.f); o1.w = fmaxf(a1.w + b1.w, 0.f);
    float4* op = (float4*)(out + (size_t)n * HW) + lane * 2;
    op[0] = o0; op[1] = o1;
}

// ---------------- host launcher ----------------
extern "C" void kernel_launch(void* const* d_in, const int* in_sizes, int n_in,
                              void* d_out, int out_size) {
    const float* x   = (const float*)d_in[0];
    const void*  ei  = d_in[1];
    const float* W1  = (const float*)d_in[2];
    const float* as1 = (const float*)d_in[3];
    const float* ad1 = (const float*)d_in[4];
    const float* b1  = (const float*)d_in[5];
    const float* W2  = (const float*)d_in[6];
    const float* as2 = (const float*)d_in[7];
    const float* ad2 = (const float*)d_in[8];
    const float* b2  = (const float*)d_in[9];
    const float* W3  = (const float*)d_in[10];
    const float* as3 = (const float*)d_in[11];
    const float* ad3 = (const float*)d_in[12];
    const float* b3  = (const float*)d_in[13];
    const float* Wm1 = (const float*)d_in[14];
    const float* bm1 = (const float*)d_in[15];
    const float* Wm2 = (const float*)d_in[16];
    const float* bm2 = (const float*)d_in[17];
    float* out = (float*)d_out;

    float *p_h, *p_feat, *p_oscr, *p_srcl, *p_dstl, *p_denom, *p_coef;
    int *p_src2, *p_dst2, *p_srcs, *p_counts, *p_fill, *p_rowptr, *p_bsum;
    cudaGetSymbolAddress((void**)&p_h, g_h);
    cudaGetSymbolAddress((void**)&p_feat, g_feat);
    cudaGetSymbolAddress((void**)&p_oscr, g_oscr);
    cudaGetSymbolAddress((void**)&p_srcl, g_srcl);
    cudaGetSymbolAddress((void**)&p_dstl, g_dstl);
    cudaGetSymbolAddress((void**)&p_denom, g_denom);
    cudaGetSymbolAddress((void**)&p_coef, g_coef);
    cudaGetSymbolAddress((void**)&p_src2, g_src2);
    cudaGetSymbolAddress((void**)&p_dst2, g_dst2);
    cudaGetSymbolAddress((void**)&p_srcs, g_src_sorted);
    cudaGetSymbolAddress((void**)&p_counts, g_counts);
    cudaGetSymbolAddress((void**)&p_fill, g_fill);
    cudaGetSymbolAddress((void**)&p_rowptr, g_rowptr);
    cudaGetSymbolAddress((void**)&p_bsum, g_bsum);

    // --- CSR build ---
    k_detect<<<1, 512>>>(ei);
    k_zero_counts<<<(NN + 255) / 256, 256>>>(p_counts, NN);
    k_build_edges<<<(EE + 255) / 256, 256>>>(ei, p_src2, p_dst2, p_counts);
    k_blocksum<<<SCAN_NB, SCAN_B>>>(p_counts, p_bsum);
    k_scan_top<<<1, SCAN_B>>>(p_bsum);
    k_scan_final<<<SCAN_NB, SCAN_B>>>(p_counts, p_bsum, p_rowptr, p_fill);
    k_scatter<<<(EE + 255) / 256, 256>>>(p_src2, p_dst2, p_fill, p_srcs);

    const int warpsGrid = (NN * 32 + 255) / 256;
    const int attnGrid  = (NN * 4 + 255) / 256;
    const int NBY = NNP / GBM;                 // 391
    dim3 gGrid(HW / GBN, NBY);                 // (2, 391)
    dim3 gGridOut(1, NBY);

    // --- GAT layer 1 (K = 128) ---
    k_gemm2<<<gGrid, 256>>>(x, W1, p_h, NN, HW, IN_FEAT, HW);
    k_logits<<<warpsGrid, 256>>>(p_h, as1, ad1, p_srcl, p_dstl);
    k_attn<<<attnGrid, 256>>>(p_srcl, p_dstl, p_rowptr, p_srcs, p_coef, p_denom);
    k_agg<<<warpsGrid, 256>>>(p_h, p_rowptr, p_srcs, p_coef, p_denom, b1, p_feat);

    // --- GAT layer 2 ---
    k_gemm2<<<gGrid, 256>>>(p_feat, W2, p_h, NN, HW, HW, HW);
    k_logits<<<warpsGrid, 256>>>(p_h, as2, ad2, p_srcl, p_dstl);
    k_attn<<<attnGrid, 256>>>(p_srcl, p_dstl, p_rowptr, p_srcs, p_coef, p_denom);
    k_agg<<<warpsGrid, 256>>>(p_h, p_rowptr, p_srcs, p_coef, p_denom, b2, p_feat);

    // --- GAT layer 3 ---
    k_gemm2<<<gGrid, 256>>>(p_feat, W3, p_h, NN, HW, HW, HW);
    k_logits<<<warpsGrid, 256>>>(p_h, as3, ad3, p_srcl, p_dstl);
    k_attn<<<attnGrid, 256>>>(p_srcl, p_dstl, p_rowptr, p_srcs, p_coef, p_denom);
    k_agg<<<warpsGrid, 256>>>(p_h, p_rowptr, p_srcs, p_coef, p_denom, b3, p_feat);

    // --- MLP head ---
    k_gemm2<<<gGrid, 256>>>(p_feat, Wm1, p_h, NN, HW, HW, HW);
    k_biasrelu<<<(NN * 64 + 255) / 256, 256>>>(p_h, bm1);
    k_gemm2<<<gGridOut, 256>>>(p_h, Wm2, p_oscr, NN, OUTF, HW, 128);
    k_copyout<<<(NN * OUTF + 255) / 256, 256>>>(p_oscr, bm2, out);
}

// round 10
// speedup vs baseline: 1.5967x; 1.5967x over previous
#include <cuda_runtime.h>
#include <cuda_bf16.h>
#include <mma.h>
#include <cstdint>

using namespace nvcuda;

#define NN 50000
#define NE 800000
#define EE (NE + NN)   // edges + self loops = 850000
#define HW 256
#define IN_FEAT 128
#define OUTF 40

// ---------------- scratch (static device globals; no runtime allocation) ----
__device__ float g_h[NN * HW];      // transformed features  (x @ W)
__device__ float g_feat[NN * HW];   // layer output / next layer input
__device__ float g_srcl[NN * 4];
__device__ float g_dstl[NN * 4];
__device__ float g_denom[NN * 4];
__device__ float g_coef[EE * 4];    // per-edge (sorted order) exp values
__device__ int   g_src2[EE];
__device__ int   g_dst2[EE];
__device__ int   g_src_sorted[EE];
__device__ int   g_counts[NN];
__device__ int   g_fill[NN];
__device__ int   g_rowptr[NN + 1];
__device__ int   g_bsum[256];
__device__ int   g_is64;            // edge_index dtype flag

// ---------------- dtype detection (parallel — no serial latency chain) -----
__global__ void k_detect(const void* __restrict__ ei) {
    __shared__ int bad;
    if (threadIdx.x == 0) bad = 0;
    __syncthreads();
    const long long* p = (const long long*)ei;
    long long v = p[threadIdx.x];              // first 512 int64 = 4KB, safe either dtype
    if (v < 0 || v >= (long long)NN) bad = 1;
    __syncthreads();
    if (threadIdx.x == 0) g_is64 = bad ? 0 : 1;
}

// ---------------- CSR build ----------------
__global__ void k_zero_counts(int* counts, int n) {
    int i = blockIdx.x * blockDim.x + threadIdx.x;
    if (i < n) counts[i] = 0;
}

__global__ void k_build_edges(const void* __restrict__ ei,
                              int* __restrict__ src2, int* __restrict__ dst2,
                              int* __restrict__ counts) {
    int e = blockIdx.x * blockDim.x + threadIdx.x;
    if (e >= EE) return;
    int s, d;
    if (e < NE) {
        if (g_is64) {
            const long long* p = (const long long*)ei;
            s = (int)p[e]; d = (int)p[NE + e];
        } else {
            const int* p = (const int*)ei;
            s = p[e]; d = p[NE + e];
        }
        s = min(max(s, 0), NN - 1);
        d = min(max(d, 0), NN - 1);
    } else {
        s = d = e - NE;          // self loop
    }
    src2[e] = s;
    dst2[e] = d;
    atomicAdd(&counts[d], 1);
}

// ---------------- hierarchical exclusive scan ------------------------------
#define SCAN_B 256
#define SCAN_NB ((NN + SCAN_B - 1) / SCAN_B)   // 196

__global__ void k_blocksum(const int* __restrict__ counts, int* __restrict__ bsum) {
    __shared__ int s[SCAN_B];
    int i = blockIdx.x * SCAN_B + threadIdx.x;
    s[threadIdx.x] = (i < NN) ? counts[i] : 0;
    __syncthreads();
    for (int off = 128; off > 0; off >>= 1) {
        if (threadIdx.x < off) s[threadIdx.x] += s[threadIdx.x + off];
        __syncthreads();
    }
    if (threadIdx.x == 0) bsum[blockIdx.x] = s[0];
}

__global__ void k_scan_top(int* __restrict__ bsum) {   // 1 block, 256 threads
    __shared__ int s[SCAN_B];
    int v = (threadIdx.x < SCAN_NB) ? bsum[threadIdx.x] : 0;
    s[threadIdx.x] = v;
    __syncthreads();
    for (int off = 1; off < SCAN_B; off <<= 1) {
        int t = (threadIdx.x >= off) ? s[threadIdx.x - off] : 0;
        __syncthreads();
        s[threadIdx.x] += t;
        __syncthreads();
    }
    if (threadIdx.x < SCAN_NB) bsum[threadIdx.x] = s[threadIdx.x] - v;  // exclusive
}

__global__ void k_scan_final(const int* __restrict__ counts, const int* __restrict__ bsum,
                             int* __restrict__ rowptr, int* __restrict__ fill) {
    __shared__ int s[SCAN_B];
    int i = blockIdx.x * SCAN_B + threadIdx.x;
    int v = (i < NN) ? counts[i] : 0;
    s[threadIdx.x] = v;
    __syncthreads();
    for (int off = 1; off < SCAN_B; off <<= 1) {
        int t = (threadIdx.x >= off) ? s[threadIdx.x - off] : 0;
        __syncthreads();
        s[threadIdx.x] += t;
        __syncthreads();
    }
    int excl = bsum[blockIdx.x] + s[threadIdx.x] - v;
    if (i < NN) { rowptr[i] = excl; fill[i] = excl; }
    if (i == NN - 1) rowptr[NN] = excl + v;
}

__global__ void k_scatter(const int* __restrict__ src2, const int* __restrict__ dst2,
                          int* __restrict__ fill, int* __restrict__ src_sorted) {
    int e = blockIdx.x * blockDim.x + threadIdx.x;
    if (e >= EE) return;
    int d = dst2[e];
    int p = atomicAdd(&fill[d], 1);
    src_sorted[p] = src2[e];
}

// ---------------- tf32 tensor-core GEMM (validated 840us config) -----------
// block 256 threads = 8 warps (4 along M x 2 along N); warp owns 32x32;
// block tile 128x64; K step 16; smem-staged epilogue.
#define GBM 128
#define GBN 64
#define GBK 16

__global__ __launch_bounds__(256) void k_gemm_tf32(
    const float* __restrict__ A, const float* __restrict__ B,
    float* __restrict__ C, int M, int N, int K,
    const float* __restrict__ bias, int do_relu)
{
    __shared__ float As[GBM][GBK + 4];   // 128 x 20
    __shared__ float Bs[GBK][GBN + 4];   // 16 x 68
    __shared__ float Cs[GBM][GBN];       // 128 x 64

    int tid = threadIdx.x;
    int warp = tid >> 5;
    int wm = warp >> 1;      // 0..3
    int wn = warp & 1;       // 0..1
    int row0 = blockIdx.y * GBM;
    int col0 = blockIdx.x * GBN;

    wmma::fragment<wmma::accumulator, 16, 16, 8, float> acc[2][2];
#pragma unroll
    for (int i = 0; i < 2; i++)
#pragma unroll
        for (int j = 0; j < 2; j++) wmma::fill_fragment(acc[i][j], 0.0f);

    for (int k0 = 0; k0 < K; k0 += GBK) {
        // A tile: 128x16 floats = 512 float4; 2 per thread
#pragma unroll
        for (int t = 0; t < 2; t++) {
            int idx = tid + t * 256;
            int r = idx >> 2;
            int c4 = (idx & 3) * 4;
            float4 v = make_float4(0.f, 0.f, 0.f, 0.f);
            if (row0 + r < M)
                v = *(const float4*)(A + (size_t)(row0 + r) * K + k0 + c4);
            As[r][c4 + 0] = wmma::__float_to_tf32(v.x);
            As[r][c4 + 1] = wmma::__float_to_tf32(v.y);
            As[r][c4 + 2] = wmma::__float_to_tf32(v.z);
            As[r][c4 + 3] = wmma::__float_to_tf32(v.w);
        }
        // B tile: 16x64; 4 scalars per thread (guards for N=40 tail)
        {
            int r = tid >> 4;
            int c0 = (tid & 15) * 4;
#pragma unroll
            for (int j = 0; j < 4; j++) {
                int c = c0 + j;
                float v = 0.f;
                if (col0 + c < N) v = B[(size_t)(k0 + r) * N + col0 + c];
                Bs[r][c] = wmma::__float_to_tf32(v);
            }
        }
        __syncthreads();

#pragma unroll
        for (int kk = 0; kk < GBK; kk += 8) {
            wmma::fragment<wmma::matrix_a, 16, 16, 8, wmma::precision::tf32, wmma::row_major> a[2];
            wmma::fragment<wmma::matrix_b, 16, 16, 8, wmma::precision::tf32, wmma::row_major> b[2];
            wmma::load_matrix_sync(a[0], &As[wm * 32 +  0][kk], GBK + 4);
            wmma::load_matrix_sync(a[1], &As[wm * 32 + 16][kk], GBK + 4);
            wmma::load_matrix_sync(b[0], &Bs[kk][wn * 32 +  0], GBN + 4);
            wmma::load_matrix_sync(b[1], &Bs[kk][wn * 32 + 16], GBN + 4);
#pragma unroll
            for (int i = 0; i < 2; i++)
#pragma unroll
                for (int j = 0; j < 2; j++)
                    wmma::mma_sync(acc[i][j], a[i], b[j], acc[i][j]);
        }
        __syncthreads();
    }

    // epilogue via smem (bias / relu / boundary guards)
#pragma unroll
    for (int i = 0; i < 2; i++)
#pragma unroll
        for (int j = 0; j < 2; j++)
            wmma::store_matrix_sync(&Cs[wm * 32 + i * 16][wn * 32 + j * 16],
                                    acc[i][j], GBN, wmma::mem_row_major);
    __syncthreads();

#pragma unroll
    for (int it = 0; it < 8; it++) {
        int idx = tid + it * 256;        // 0..2047
        int r = idx >> 4;                // 0..127
        int c4 = (idx & 15) * 4;
        int gr = row0 + r;
        if (gr >= M) continue;
        float4 v = *(const float4*)&Cs[r][c4];
        int gc = col0 + c4;
        float* vv = &v.x;
        if (bias) {
#pragma unroll
            for (int j = 0; j < 4; j++)
                if (gc + j < N) vv[j] += bias[gc + j];
        }
        if (do_relu) {
#pragma unroll
            for (int j = 0; j < 4; j++) vv[j] = fmaxf(vv[j], 0.f);
        }
        if (gc + 4 <= N) {
            *(float4*)(C + (size_t)gr * N + gc) = v;
        } else {
#pragma unroll
            for (int j = 0; j < 4; j++)
                if (gc + j < N) C[(size_t)gr * N + gc + j] = vv[j];
        }
    }
}

// ---------------- per-node attention logits: warp per node ----------------
__global__ void k_logits(const float* __restrict__ h, const float* __restrict__ a_s,
                         const float* __restrict__ a_d,
                         float* __restrict__ srcl, float* __restrict__ dstl) {
    int warp = (blockIdx.x * blockDim.x + threadIdx.x) >> 5;
    int lane = threadIdx.x & 31;
    if (warp >= NN) return;
    int n = warp;
    const float4* hp = (const float4*)(h + (size_t)n * HW) + lane * 2;
    float4 v0 = hp[0], v1 = hp[1];
    int head = lane >> 3, sub = lane & 7;
    const float4* ap = (const float4*)(a_s + head * 64 + sub * 8);
    const float4* dp = (const float4*)(a_d + head * 64 + sub * 8);
    float4 s0 = ap[0], s1 = ap[1];
    float4 d0 = dp[0], d1 = dp[1];
    float ps = v0.x * s0.x + v0.y * s0.y + v0.z * s0.z + v0.w * s0.w
             + v1.x * s1.x + v1.y * s1.y + v1.z * s1.z + v1.w * s1.w;
    float pd = v0.x * d0.x + v0.y * d0.y + v0.z * d0.z + v0.w * d0.w
             + v1.x * d1.x + v1.y * d1.y + v1.z * d1.z + v1.w * d1.w;
#pragma unroll
    for (int off = 4; off >= 1; off >>= 1) {
        ps += __shfl_down_sync(0xffffffffu, ps, off, 8);
        pd += __shfl_down_sync(0xffffffffu, pd, off, 8);
    }
    if (sub == 0) {
        srcl[n * 4 + head] = ps;
        dstl[n * 4 + head] = pd;
    }
}

// ---------------- segment softmax: one thread per (node, head) -------------
__global__ void k_attn(const float* __restrict__ srcl, const float* __restrict__ dstl,
                       const int* __restrict__ rowptr, const int* __restrict__ src_sorted,
                       float* __restrict__ coef, float* __restrict__ denom) {
    int t = blockIdx.x * blockDim.x + threadIdx.x;
    if (t >= NN * 4) return;
    int n = t >> 2, hd = t & 3;
    float dl = dstl[t];
    int b = rowptr[n], e = rowptr[n + 1];
    float mx = -1e30f;
    for (int i = b; i < e; i++) {
        int s = src_sorted[i];
        float a = srcl[s * 4 + hd] + dl;
        a = a > 0.f ? a : 0.2f * a;       // leaky_relu(0.2)
        coef[i * 4 + hd] = a;
        mx = fmaxf(mx, a);
    }
    float sum = 0.f;
    for (int i = b; i < e; i++) {
        float ev = __expf(coef[i * 4 + hd] - mx);
        coef[i * 4 + hd] = ev;
        sum += ev;
    }
    denom[t] = sum;
}

// ---------------- aggregation: warp per destination node, no atomics -------
__global__ void k_agg(const float* __restrict__ h, const int* __restrict__ rowptr,
                      const int* __restrict__ src_sorted, const float* __restrict__ coef,
                      const float* __restrict__ denom, const float* __restrict__ bias,
                      float* __restrict__ out) {
    int warp = (blockIdx.x * blockDim.x + threadIdx.x) >> 5;
    int lane = threadIdx.x & 31;
    if (warp >= NN) return;
    int n = warp;
    int head = lane >> 3;
    float rinv = 1.0f / denom[n * 4 + head];
    int b = rowptr[n], e = rowptr[n + 1];
    float4 a0 = make_float4(0.f, 0.f, 0.f, 0.f);
    float4 a1 = make_float4(0.f, 0.f, 0.f, 0.f);
    for (int i = b; i < e; i++) {
        int s = src_sorted[i];
        float4 cq = ((const float4*)coef)[i];
        float c = (head == 0) ? cq.x : (head == 1) ? cq.y : (head == 2) ? cq.z : cq.w;
        c *= rinv;
        const float4* hp = (const float4*)(h + (size_t)s * HW) + lane * 2;
        float4 v0 = hp[0], v1 = hp[1];
        a0.x += v0.x * c; a0.y += v0.y * c; a0.z += v0.z * c; a0.w += v0.w * c;
        a1.x += v1.x * c; a1.y += v1.y * c; a1.z += v1.z * c; a1.w += v1.w * c;
    }
    const float4* bp = (const float4*)bias + lane * 2;
    float4 b0 = bp[0], b1 = bp[1];
    float4 o0, o1;
    o0.x = fmaxf(a0.x + b0.x, 0.f); o0.y = fmaxf(a0.y + b0.y, 0.f);
    o0.z = fmaxf(a0.z + b0.z, 0.f); o0.w = fmaxf(a0.w + b0.w, 0.f);
    o1.x = fmaxf(a1.x + b1.x, 0.f); o1.y = fmaxf(a1.y + b1.y, 0.f);
    o1.z = fmaxf(a1.z + b1.z, 0.f); o1.w = fmaxf(a1.w + b1.w, 0.f);
    float4* op = (float4*)(out + (size_t)n * HW) + lane * 2;
    op[0] = o0; op[1] = o1;
}

// ---------------- host launcher ----------------
extern "C" void kernel_launch(void* const* d_in, const int* in_sizes, int n_in,
                              void* d_out, int out_size) {
    const float* x   = (const float*)d_in[0];
    const void*  ei  = d_in[1];
    const float* W1  = (const float*)d_in[2];
    const float* as1 = (const float*)d_in[3];
    const float* ad1 = (const float*)d_in[4];
    const float* b1  = (const float*)d_in[5];
    const float* W2  = (const float*)d_in[6];
    const float* as2 = (const float*)d_in[7];
    const float* ad2 = (const float*)d_in[8];
    const float* b2  = (const float*)d_in[9];
    const float* W3  = (const float*)d_in[10];
    const float* as3 = (const float*)d_in[11];
    const float* ad3 = (const float*)d_in[12];
    const float* b3  = (const float*)d_in[13];
    const float* Wm1 = (const float*)d_in[14];
    const float* bm1 = (const float*)d_in[15];
    const float* Wm2 = (const float*)d_in[16];
    const float* bm2 = (const float*)d_in[17];
    float* out = (float*)d_out;

    float *p_h, *p_feat, *p_srcl, *p_dstl, *p_denom, *p_coef;
    int *p_src2, *p_dst2, *p_srcs, *p_counts, *p_fill, *p_rowptr, *p_bsum;
    cudaGetSymbolAddress((void**)&p_h, g_h);
    cudaGetSymbolAddress((void**)&p_feat, g_feat);
    cudaGetSymbolAddress((void**)&p_srcl, g_srcl);
    cudaGetSymbolAddress((void**)&p_dstl, g_dstl);
    cudaGetSymbolAddress((void**)&p_denom, g_denom);
    cudaGetSymbolAddress((void**)&p_coef, g_coef);
    cudaGetSymbolAddress((void**)&p_src2, g_src2);
    cudaGetSymbolAddress((void**)&p_dst2, g_dst2);
    cudaGetSymbolAddress((void**)&p_srcs, g_src_sorted);
    cudaGetSymbolAddress((void**)&p_counts, g_counts);
    cudaGetSymbolAddress((void**)&p_fill, g_fill);
    cudaGetSymbolAddress((void**)&p_rowptr, g_rowptr);
    cudaGetSymbolAddress((void**)&p_bsum, g_bsum);

    // --- CSR build (once per call; reused by all 3 layers) ---
    k_detect<<<1, 512>>>(ei);
    k_zero_counts<<<(NN + 255) / 256, 256>>>(p_counts, NN);
    k_build_edges<<<(EE + 255) / 256, 256>>>(ei, p_src2, p_dst2, p_counts);
    k_blocksum<<<SCAN_NB, SCAN_B>>>(p_counts, p_bsum);
    k_scan_top<<<1, SCAN_B>>>(p_bsum);
    k_scan_final<<<SCAN_NB, SCAN_B>>>(p_counts, p_bsum, p_rowptr, p_fill);
    k_scatter<<<(EE + 255) / 256, 256>>>(p_src2, p_dst2, p_fill, p_srcs);

    const int warpsGrid = (NN * 32 + 255) / 256;
    const int attnGrid  = (NN * 4 + 255) / 256;
    dim3 gGrid(HW / GBN, (NN + GBM - 1) / GBM);          // (4, 391)
    dim3 gGridOut((OUTF + GBN - 1) / GBN, (NN + GBM - 1) / GBM);  // (1, 391)

    // --- GAT layer 1 (K = 128) ---
    k_gemm_tf32<<<gGrid, 256>>>(x, W1, p_h, NN, HW, IN_FEAT, nullptr, 0);
    k_logits<<<warpsGrid, 256>>>(p_h, as1, ad1, p_srcl, p_dstl);
    k_attn<<<attnGrid, 256>>>(p_srcl, p_dstl, p_rowptr, p_srcs, p_coef, p_denom);
    k_agg<<<warpsGrid, 256>>>(p_h, p_rowptr, p_srcs, p_coef, p_denom, b1, p_feat);

    // --- GAT layer 2 ---
    k_gemm_tf32<<<gGrid, 256>>>(p_feat, W2, p_h, NN, HW, HW, nullptr, 0);
    k_logits<<<warpsGrid, 256>>>(p_h, as2, ad2, p_srcl, p_dstl);
    k_attn<<<attnGrid, 256>>>(p_srcl, p_dstl, p_rowptr, p_srcs, p_coef, p_denom);
    k_agg<<<warpsGrid, 256>>>(p_h, p_rowptr, p_srcs, p_coef, p_denom, b2, p_feat);

    // --- GAT layer 3 ---
    k_gemm_tf32<<<gGrid, 256>>>(p_feat, W3, p_h, NN, HW, HW, nullptr, 0);
    k_logits<<<warpsGrid, 256>>>(p_h, as3, ad3, p_srcl, p_dstl);
    k_attn<<<attnGrid, 256>>>(p_srcl, p_dstl, p_rowptr, p_srcs, p_coef, p_denom);
    k_agg<<<warpsGrid, 256>>>(p_h, p_rowptr, p_srcs, p_coef, p_denom, b3, p_feat);

    // --- MLP head ---
    k_gemm_tf32<<<gGrid, 256>>>(p_feat, Wm1, p_h, NN, HW, HW, bm1, 1);
    k_gemm_tf32<<<gGridOut, 256>>>(p_h, Wm2, out, NN, OUTF, HW, bm2, 0);
}

// round 11
// speedup vs baseline: 1.6404x; 1.0274x over previous
#include <cuda_runtime.h>
#include <cuda_bf16.h>
#include <mma.h>
#include <cstdint>

using namespace nvcuda;

#define NN 50000
#define NNP 50048              // 391*128: padded rows for guard-free direct GEMM stores
#define NE 800000
#define EE (NE + NN)           // edges + self loops = 850000
#define HW 256
#define IN_FEAT 128
#define OUTF 40

// ---------------- scratch ----------------
__device__ float g_h[NNP * HW];      // transformed features  (x @ W); pad rows scratch
__device__ float g_feat[NN * HW];    // layer output / next layer input
__device__ float g_srcl[NN * 4];
__device__ float g_dstl[NN * 4];
__device__ float g_amax[NN * 4];
__device__ int   g_src2[EE];
__device__ int   g_dst2[EE];
__device__ int   g_src_sorted[EE];
__device__ int   g_counts[NN];
__device__ int   g_fill[NN];
__device__ int   g_rowptr[NN + 1];
__device__ int   g_bsum[256];
__device__ int   g_is64;

// ---------------- dtype detection ----------------
__global__ void k_detect(const void* __restrict__ ei) {
    __shared__ int bad;
    if (threadIdx.x == 0) bad = 0;
    __syncthreads();
    const long long* p = (const long long*)ei;
    long long v = p[threadIdx.x];
    if (v < 0 || v >= (long long)NN) bad = 1;
    __syncthreads();
    if (threadIdx.x == 0) g_is64 = bad ? 0 : 1;
}

// ---------------- CSR build ----------------
__global__ void k_zero_counts(int* counts, int n) {
    int i = blockIdx.x * blockDim.x + threadIdx.x;
    if (i < n) counts[i] = 0;
}

__global__ void k_build_edges(const void* __restrict__ ei,
                              int* __restrict__ src2, int* __restrict__ dst2,
                              int* __restrict__ counts) {
    int e = blockIdx.x * blockDim.x + threadIdx.x;
    if (e >= EE) return;
    int s, d;
    if (e < NE) {
        if (g_is64) {
            const long long* p = (const long long*)ei;
            s = (int)p[e]; d = (int)p[NE + e];
        } else {
            const int* p = (const int*)ei;
            s = p[e]; d = p[NE + e];
        }
        s = min(max(s, 0), NN - 1);
        d = min(max(d, 0), NN - 1);
    } else {
        s = d = e - NE;
    }
    src2[e] = s;
    dst2[e] = d;
    atomicAdd(&counts[d], 1);
}

// ---------------- hierarchical exclusive scan ----------------
#define SCAN_B 256
#define SCAN_NB ((NN + SCAN_B - 1) / SCAN_B)   // 196

__global__ void k_blocksum(const int* __restrict__ counts, int* __restrict__ bsum) {
    __shared__ int s[SCAN_B];
    int i = blockIdx.x * SCAN_B + threadIdx.x;
    s[threadIdx.x] = (i < NN) ? counts[i] : 0;
    __syncthreads();
    for (int off = 128; off > 0; off >>= 1) {
        if (threadIdx.x < off) s[threadIdx.x] += s[threadIdx.x + off];
        __syncthreads();
    }
    if (threadIdx.x == 0) bsum[blockIdx.x] = s[0];
}

__global__ void k_scan_top(int* __restrict__ bsum) {
    __shared__ int s[SCAN_B];
    int v = (threadIdx.x < SCAN_NB) ? bsum[threadIdx.x] : 0;
    s[threadIdx.x] = v;
    __syncthreads();
    for (int off = 1; off < SCAN_B; off <<= 1) {
        int t = (threadIdx.x >= off) ? s[threadIdx.x - off] : 0;
        __syncthreads();
        s[threadIdx.x] += t;
        __syncthreads();
    }
    if (threadIdx.x < SCAN_NB) bsum[threadIdx.x] = s[threadIdx.x] - v;
}

__global__ void k_scan_final(const int* __restrict__ counts, const int* __restrict__ bsum,
                             int* __restrict__ rowptr, int* __restrict__ fill) {
    __shared__ int s[SCAN_B];
    int i = blockIdx.x * SCAN_B + threadIdx.x;
    int v = (i < NN) ? counts[i] : 0;
    s[threadIdx.x] = v;
    __syncthreads();
    for (int off = 1; off < SCAN_B; off <<= 1) {
        int t = (threadIdx.x >= off) ? s[threadIdx.x - off] : 0;
        __syncthreads();
        s[threadIdx.x] += t;
        __syncthreads();
    }
    int excl = bsum[blockIdx.x] + s[threadIdx.x] - v;
    if (i < NN) { rowptr[i] = excl; fill[i] = excl; }
    if (i == NN - 1) rowptr[NN] = excl + v;
}

__global__ void k_scatter(const int* __restrict__ src2, const int* __restrict__ dst2,
                          int* __restrict__ fill, int* __restrict__ src_sorted) {
    int e = blockIdx.x * blockDim.x + threadIdx.x;
    if (e >= EE) return;
    int d = dst2[e];
    int p = atomicAdd(&fill[d], 1);
    src_sorted[p] = src2[e];
}

// ---------------- GEMM v3 "big": C[M(pad),256] = A[M,K] @ B[K,256] ---------
// 512 threads / 16 warps (4x4); warp tile 32x32 (2x2 frags, SAME per-thread
// footprint as validated v1); block tile 128x128; BK=32; direct frag stores.
#define BGM 128
#define BGN 128
#define BGK 32

__global__ __launch_bounds__(512) void k_gemm_big(
    const float* __restrict__ A, const float* __restrict__ B,
    float* __restrict__ C, int M, int K)
{
    __shared__ float As[BGM][BGK + 4];   // 128 x 36
    __shared__ float Bs[BGK][BGN + 4];   // 32 x 132

    int tid = threadIdx.x;
    int warp = tid >> 5;
    int wm = warp >> 2;          // 0..3
    int wn = warp & 3;           // 0..3
    int row0 = blockIdx.y * BGM;
    int col0 = blockIdx.x * BGN;

    wmma::fragment<wmma::accumulator, 16, 16, 8, float> acc[2][2];
#pragma unroll
    for (int i = 0; i < 2; i++)
#pragma unroll
        for (int j = 0; j < 2; j++) wmma::fill_fragment(acc[i][j], 0.0f);

    for (int k0 = 0; k0 < K; k0 += BGK) {
        // A tile: 128x32 = 1024 float4; 2 per thread
#pragma unroll
        for (int t = 0; t < 2; t++) {
            int idx = tid + t * 512;
            int r = idx >> 3, c4 = (idx & 7) * 4;
            float4 v = make_float4(0.f, 0.f, 0.f, 0.f);
            if (row0 + r < M)
                v = *(const float4*)(A + (size_t)(row0 + r) * K + k0 + c4);
            As[r][c4 + 0] = wmma::__float_to_tf32(v.x);
            As[r][c4 + 1] = wmma::__float_to_tf32(v.y);
            As[r][c4 + 2] = wmma::__float_to_tf32(v.z);
            As[r][c4 + 3] = wmma::__float_to_tf32(v.w);
        }
        // B tile: 32x128 = 1024 float4; 2 per thread (N=256 exact, no guards)
#pragma unroll
        for (int t = 0; t < 2; t++) {
            int idx = tid + t * 512;
            int r = idx >> 5, c4 = (idx & 31) * 4;
            float4 v = *(const float4*)(B + (size_t)(k0 + r) * HW + col0 + c4);
            Bs[r][c4 + 0] = wmma::__float_to_tf32(v.x);
            Bs[r][c4 + 1] = wmma::__float_to_tf32(v.y);
            Bs[r][c4 + 2] = wmma::__float_to_tf32(v.z);
            Bs[r][c4 + 3] = wmma::__float_to_tf32(v.w);
        }
        __syncthreads();

#pragma unroll
        for (int kk = 0; kk < BGK; kk += 8) {
            wmma::fragment<wmma::matrix_a, 16, 16, 8, wmma::precision::tf32, wmma::row_major> a[2];
            wmma::fragment<wmma::matrix_b, 16, 16, 8, wmma::precision::tf32, wmma::row_major> b[2];
            wmma::load_matrix_sync(a[0], &As[wm * 32 +  0][kk], BGK + 4);
            wmma::load_matrix_sync(a[1], &As[wm * 32 + 16][kk], BGK + 4);
            wmma::load_matrix_sync(b[0], &Bs[kk][wn * 32 +  0], BGN + 4);
            wmma::load_matrix_sync(b[1], &Bs[kk][wn * 32 + 16], BGN + 4);
#pragma unroll
            for (int i = 0; i < 2; i++)
#pragma unroll
                for (int j = 0; j < 2; j++)
                    wmma::mma_sync(acc[i][j], a[i], b[j], acc[i][j]);
        }
        __syncthreads();
    }

    // direct stores — C row-padded to NNP, ldc = 256, all tiles in-bounds
#pragma unroll
    for (int i = 0; i < 2; i++)
#pragma unroll
        for (int j = 0; j < 2; j++) {
            int r = row0 + wm * 32 + i * 16;
            int c = col0 + wn * 32 + j * 16;
            wmma::store_matrix_sync(C + (size_t)r * HW + c, acc[i][j], HW,
                                    wmma::mem_row_major);
        }
}

// ---------------- GEMM v1 (validated) for the N=40 head GEMM ----------------
#define GBM 128
#define GBN 64
#define GBK 16

__global__ __launch_bounds__(256) void k_gemm_tf32(
    const float* __restrict__ A, const float* __restrict__ B,
    float* __restrict__ C, int M, int N, int K,
    const float* __restrict__ bias, int do_relu)
{
    __shared__ float As[GBM][GBK + 4];
    __shared__ float Bs[GBK][GBN + 4];
    __shared__ float Cs[GBM][GBN];

    int tid = threadIdx.x;
    int warp = tid >> 5;
    int wm = warp >> 1;
    int wn = warp & 1;
    int row0 = blockIdx.y * GBM;
    int col0 = blockIdx.x * GBN;

    wmma::fragment<wmma::accumulator, 16, 16, 8, float> acc[2][2];
#pragma unroll
    for (int i = 0; i < 2; i++)
#pragma unroll
        for (int j = 0; j < 2; j++) wmma::fill_fragment(acc[i][j], 0.0f);

    for (int k0 = 0; k0 < K; k0 += GBK) {
#pragma unroll
        for (int t = 0; t < 2; t++) {
            int idx = tid + t * 256;
            int r = idx >> 2;
            int c4 = (idx & 3) * 4;
            float4 v = make_float4(0.f, 0.f, 0.f, 0.f);
            if (row0 + r < M)
                v = *(const float4*)(A + (size_t)(row0 + r) * K + k0 + c4);
            As[r][c4 + 0] = wmma::__float_to_tf32(v.x);
            As[r][c4 + 1] = wmma::__float_to_tf32(v.y);
            As[r][c4 + 2] = wmma::__float_to_tf32(v.z);
            As[r][c4 + 3] = wmma::__float_to_tf32(v.w);
        }
        {
            int r = tid >> 4;
            int c0 = (tid & 15) * 4;
#pragma unroll
            for (int j = 0; j < 4; j++) {
                int c = c0 + j;
                float v = 0.f;
                if (col0 + c < N) v = B[(size_t)(k0 + r) * N + col0 + c];
                Bs[r][c] = wmma::__float_to_tf32(v);
            }
        }
        __syncthreads();

#pragma unroll
        for (int kk = 0; kk < GBK; kk += 8) {
            wmma::fragment<wmma::matrix_a, 16, 16, 8, wmma::precision::tf32, wmma::row_major> a[2];
            wmma::fragment<wmma::matrix_b, 16, 16, 8, wmma::precision::tf32, wmma::row_major> b[2];
            wmma::load_matrix_sync(a[0], &As[wm * 32 +  0][kk], GBK + 4);
            wmma::load_matrix_sync(a[1], &As[wm * 32 + 16][kk], GBK + 4);
            wmma::load_matrix_sync(b[0], &Bs[kk][wn * 32 +  0], GBN + 4);
            wmma::load_matrix_sync(b[1], &Bs[kk][wn * 32 + 16], GBN + 4);
#pragma unroll
            for (int i = 0; i < 2; i++)
#pragma unroll
                for (int j = 0; j < 2; j++)
                    wmma::mma_sync(acc[i][j], a[i], b[j], acc[i][j]);
        }
        __syncthreads();
    }

#pragma unroll
    for (int i = 0; i < 2; i++)
#pragma unroll
        for (int j = 0; j < 2; j++)
            wmma::store_matrix_sync(&Cs[wm * 32 + i * 16][wn * 32 + j * 16],
                                    acc[i][j], GBN, wmma::mem_row_major);
    __syncthreads();

#pragma unroll
    for (int it = 0; it < 8; it++) {
        int idx = tid + it * 256;
        int r = idx >> 4;
        int c4 = (idx & 15) * 4;
        int gr = row0 + r;
        if (gr >= M) continue;
        float4 v = *(const float4*)&Cs[r][c4];
        int gc = col0 + c4;
        float* vv = &v.x;
        if (bias) {
#pragma unroll
            for (int j = 0; j < 4; j++)
                if (gc + j < N) vv[j] += bias[gc + j];
        }
        if (do_relu) {
#pragma unroll
            for (int j = 0; j < 4; j++) vv[j] = fmaxf(vv[j], 0.f);
        }
        if (gc + 4 <= N) {
            *(float4*)(C + (size_t)gr * N + gc) = v;
        } else {
#pragma unroll
            for (int j = 0; j < 4; j++)
                if (gc + j < N) C[(size_t)gr * N + gc + j] = vv[j];
        }
    }
}

// ---------------- bias+relu elementwise (for Wm1 epilogue) ------------------
__global__ void k_biasrelu(float* __restrict__ h, const float* __restrict__ bias) {
    int i = blockIdx.x * blockDim.x + threadIdx.x;     // over NN*64 float4
    if (i >= NN * 64) return;
    int c4 = (i & 63) * 4;
    float4 v = ((float4*)h)[i];
    const float4 b = *(const float4*)(bias + c4);
    v.x = fmaxf(v.x + b.x, 0.f); v.y = fmaxf(v.y + b.y, 0.f);
    v.z = fmaxf(v.z + b.z, 0.f); v.w = fmaxf(v.w + b.w, 0.f);
    ((float4*)h)[i] = v;
}

// ---------------- per-node attention logits: warp per node ------------------
__global__ void k_logits(const float* __restrict__ h, const float* __restrict__ a_s,
                         const float* __restrict__ a_d,
                         float* __restrict__ srcl, float* __restrict__ dstl) {
    int warp = (blockIdx.x * blockDim.x + threadIdx.x) >> 5;
    int lane = threadIdx.x & 31;
    if (warp >= NN) return;
    int n = warp;
    const float4* hp = (const float4*)(h + (size_t)n * HW) + lane * 2;
    float4 v0 = hp[0], v1 = hp[1];
    int head = lane >> 3, sub = lane & 7;
    const float4* ap = (const float4*)(a_s + head * 64 + sub * 8);
    const float4* dp = (const float4*)(a_d + head * 64 + sub * 8);
    float4 s0 = ap[0], s1 = ap[1];
    float4 d0 = dp[0], d1 = dp[1];
    float ps = v0.x * s0.x + v0.y * s0.y + v0.z * s0.z + v0.w * s0.w
             + v1.x * s1.x + v1.y * s1.y + v1.z * s1.z + v1.w * s1.w;
    float pd = v0.x * d0.x + v0.y * d0.y + v0.z * d0.z + v0.w * d0.w
             + v1.x * d1.x + v1.y * d1.y + v1.z * d1.z + v1.w * d1.w;
#pragma unroll
    for (int off = 4; off >= 1; off >>= 1) {
        ps += __shfl_down_sync(0xffffffffu, ps, off, 8);
        pd += __shfl_down_sync(0xffffffffu, pd, off, 8);
    }
    if (sub == 0) {
        srcl[n * 4 + head] = ps;
        dstl[n * 4 + head] = pd;
    }
}

// ---------------- segment max: one thread per (node, head) ------------------
__global__ void k_maxes(const float* __restrict__ srcl, const float* __restrict__ dstl,
                        const int* __restrict__ rowptr, const int* __restrict__ src_sorted,
                        float* __restrict__ amax) {
    int t = blockIdx.x * blockDim.x + threadIdx.x;
    if (t >= NN * 4) return;
    int n = t >> 2, hd = t & 3;
    float dl = dstl[t];
    int b = rowptr[n], e = rowptr[n + 1];
    float mx = -1e30f;
    for (int i = b; i < e; i++) {
        int s = src_sorted[i];
        float a = srcl[s * 4 + hd] + dl;
        a = a > 0.f ? a : 0.2f * a;       // leaky_relu(0.2)
        mx = fmaxf(mx, a);
    }
    amax[t] = mx;
}

// ---------------- fused softmax-aggregate: warp per node, no atomics --------
__global__ void k_agg_fused(const float* __restrict__ h, const int* __restrict__ rowptr,
                            const int* __restrict__ src_sorted,
                            const float* __restrict__ srcl, const float* __restrict__ dstl,
                            const float* __restrict__ amax, const float* __restrict__ bias,
                            float* __restrict__ out) {
    int warp = (blockIdx.x * blockDim.x + threadIdx.x) >> 5;
    int lane = threadIdx.x & 31;
    if (warp >= NN) return;
    int n = warp;
    int head = lane >> 3;
    float am = amax[n * 4 + head];
    float dl = dstl[n * 4 + head];
    int b = rowptr[n], e = rowptr[n + 1];
    float den = 0.f;
    float4 a0 = make_float4(0.f, 0.f, 0.f, 0.f);
    float4 a1 = make_float4(0.f, 0.f, 0.f, 0.f);
    for (int i = b; i < e; i++) {
        int s = src_sorted[i];
        float a = __ldg(&srcl[s * 4 + head]) + dl;
        a = a > 0.f ? a : 0.2f * a;
        float ev = __expf(a - am);
        den += ev;
        const float4* hp = (const float4*)(h + (size_t)s * HW) + lane * 2;
        float4 v0 = hp[0], v1 = hp[1];
        a0.x += v0.x * ev; a0.y += v0.y * ev; a0.z += v0.z * ev; a0.w += v0.w * ev;
        a1.x += v1.x * ev; a1.y += v1.y * ev; a1.z += v1.z * ev; a1.w += v1.w * ev;
    }
    float rinv = 1.0f / den;
    const float4* bp = (const float4*)bias + lane * 2;
    float4 b0 = bp[0], b1 = bp[1];
    float4 o0, o1;
    o0.x = fmaxf(a0.x * rinv + b0.x, 0.f); o0.y = fmaxf(a0.y * rinv + b0.y, 0.f);
    o0.z = fmaxf(a0.z * rinv + b0.z, 0.f); o0.w = fmaxf(a0.w * rinv + b0.w, 0.f);
    o1.x = fmaxf(a1.x * rinv + b1.x, 0.f); o1.y = fmaxf(a1.y * rinv + b1.y, 0.f);
    o1.z = fmaxf(a1.z * rinv + b1.z, 0.f); o1.w = fmaxf(a1.w * rinv + b1.w, 0.f);
    float4* op = (float4*)(out + (size_t)n * HW) + lane * 2;
    op[0] = o0; op[1] = o1;
}

// ---------------- host launcher ----------------
extern "C" void kernel_launch(void* const* d_in, const int* in_sizes, int n_in,
                              void* d_out, int out_size) {
    const float* x   = (const float*)d_in[0];
    const void*  ei  = d_in[1];
    const float* W1  = (const float*)d_in[2];
    const float* as1 = (const float*)d_in[3];
    const float* ad1 = (const float*)d_in[4];
    const float* b1  = (const float*)d_in[5];
    const float* W2  = (const float*)d_in[6];
    const float* as2 = (const float*)d_in[7];
    const float* ad2 = (const float*)d_in[8];
    const float* b2  = (const float*)d_in[9];
    const float* W3  = (const float*)d_in[10];
    const float* as3 = (const float*)d_in[11];
    const float* ad3 = (const float*)d_in[12];
    const float* b3  = (const float*)d_in[13];
    const float* Wm1 = (const float*)d_in[14];
    const float* bm1 = (const float*)d_in[15];
    const float* Wm2 = (const float*)d_in[16];
    const float* bm2 = (const float*)d_in[17];
    float* out = (float*)d_out;

    float *p_h, *p_feat, *p_srcl, *p_dstl, *p_amax;
    int *p_src2, *p_dst2, *p_srcs, *p_counts, *p_fill, *p_rowptr, *p_bsum;
    cudaGetSymbolAddress((void**)&p_h, g_h);
    cudaGetSymbolAddress((void**)&p_feat, g_feat);
    cudaGetSymbolAddress((void**)&p_srcl, g_srcl);
    cudaGetSymbolAddress((void**)&p_dstl, g_dstl);
    cudaGetSymbolAddress((void**)&p_amax, g_amax);
    cudaGetSymbolAddress((void**)&p_src2, g_src2);
    cudaGetSymbolAddress((void**)&p_dst2, g_dst2);
    cudaGetSymbolAddress((void**)&p_srcs, g_src_sorted);
    cudaGetSymbolAddress((void**)&p_counts, g_counts);
    cudaGetSymbolAddress((void**)&p_fill, g_fill);
    cudaGetSymbolAddress((void**)&p_rowptr, g_rowptr);
    cudaGetSymbolAddress((void**)&p_bsum, g_bsum);

    // --- CSR build ---
    k_detect<<<1, 512>>>(ei);
    k_zero_counts<<<(NN + 255) / 256, 256>>>(p_counts, NN);
    k_build_edges<<<(EE + 255) / 256, 256>>>(ei, p_src2, p_dst2, p_counts);
    k_blocksum<<<SCAN_NB, SCAN_B>>>(p_counts, p_bsum);
    k_scan_top<<<1, SCAN_B>>>(p_bsum);
    k_scan_final<<<SCAN_NB, SCAN_B>>>(p_counts, p_bsum, p_rowptr, p_fill);
    k_scatter<<<(EE + 255) / 256, 256>>>(p_src2, p_dst2, p_fill, p_srcs);

    const int warpsGrid = (NN * 32 + 255) / 256;
    const int maxGrid   = (NN * 4 + 255) / 256;
    dim3 bigGrid(HW / BGN, NNP / BGM);                   // (2, 391)
    dim3 outGrid(1, (NN + GBM - 1) / GBM);               // (1, 391)

    // --- GAT layer 1 (K = 128) ---
    k_gemm_big<<<bigGrid, 512>>>(x, W1, p_h, NN, IN_FEAT);
    k_logits<<<warpsGrid, 256>>>(p_h, as1, ad1, p_srcl, p_dstl);
    k_maxes<<<maxGrid, 256>>>(p_srcl, p_dstl, p_rowptr, p_srcs, p_amax);
    k_agg_fused<<<warpsGrid, 256>>>(p_h, p_rowptr, p_srcs, p_srcl, p_dstl, p_amax, b1, p_feat);

    // --- GAT layer 2 ---
    k_gemm_big<<<bigGrid, 512>>>(p_feat, W2, p_h, NN, HW);
    k_logits<<<warpsGrid, 256>>>(p_h, as2, ad2, p_srcl, p_dstl);
    k_maxes<<<maxGrid, 256>>>(p_srcl, p_dstl, p_rowptr, p_srcs, p_amax);
    k_agg_fused<<<warpsGrid, 256>>>(p_h, p_rowptr, p_srcs, p_srcl, p_dstl, p_amax, b2, p_feat);

    // --- GAT layer 3 ---
    k_gemm_big<<<bigGrid, 512>>>(p_feat, W3, p_h, NN, HW);
    k_logits<<<warpsGrid, 256>>>(p_h, as3, ad3, p_srcl, p_dstl);
    k_maxes<<<maxGrid, 256>>>(p_srcl, p_dstl, p_rowptr, p_srcs, p_amax);
    k_agg_fused<<<warpsGrid, 256>>>(p_h, p_rowptr, p_srcs, p_srcl, p_dstl, p_amax, b3, p_feat);

    // --- MLP head ---
    k_gemm_big<<<bigGrid, 512>>>(p_feat, Wm1, p_h, NN, HW);
    k_biasrelu<<<(NN * 64 + 255) / 256, 256>>>(p_h, bm1);
    k_gemm_tf32<<<outGrid, 256>>>(p_h, Wm2, out, NN, OUTF, HW, bm2, 0);
}

// round 13
// speedup vs baseline: 1.7401x; 1.0608x over previous
#include <cuda_runtime.h>
#include <cuda_bf16.h>
#include <mma.h>
#include <cstdint>

using namespace nvcuda;

#define NN 50000
#define NNP 50048              // 391*128: padded rows for guard-free direct GEMM stores
#define NE 800000
#define EE (NE + NN)           // edges + self loops = 850000
#define HW 256
#define IN_FEAT 128
#define OUTF 40

// weight scratch offsets (tf32-rounded copies)
#define W1OFF 0
#define W2OFF 32768
#define W3OFF 98304
#define WM1OFF 163840
#define WTOT 229376

// ---------------- scratch ----------------
__device__ float g_h[NNP * HW];      // transformed features  (x @ W); pad rows scratch
__device__ float g_feat[NN * HW];    // staged rounded x -> layer outputs
__device__ float g_wr[WTOT];         // tf32-rounded weights
__device__ float g_srcl[NN * 4];
__device__ float g_dstl[NN * 4];
__device__ float g_amax[NN * 4];
__device__ int   g_src2[EE];
__device__ int   g_dst2[EE];
__device__ int   g_src_sorted[EE];
__device__ int   g_counts[NN];
__device__ int   g_fill[NN];
__device__ int   g_rowptr[NN + 1];
__device__ int   g_bsum[256];
__device__ int   g_is64;

// ---------------- cp.async helpers ----------------
__device__ __forceinline__ void cp16(void* dst_smem, const void* src) {
    uint32_t sa = (uint32_t)__cvta_generic_to_shared(dst_smem);
    asm volatile("cp.async.ca.shared.global [%0], [%1], 16;\n" :: "r"(sa), "l"(src));
}
__device__ __forceinline__ void cp_commit() {
    asm volatile("cp.async.commit_group;\n");
}
template <int N>
__device__ __forceinline__ void cp_wait() {
    asm volatile("cp.async.wait_group %0;\n" :: "n"(N));
}

// ---------------- dtype detection ----------------
__global__ void k_detect(const void* __restrict__ ei) {
    __shared__ int bad;
    if (threadIdx.x == 0) bad = 0;
    __syncthreads();
    const long long* p = (const long long*)ei;
    long long v = p[threadIdx.x];
    if (v < 0 || v >= (long long)NN) bad = 1;
    __syncthreads();
    if (threadIdx.x == 0) g_is64 = bad ? 0 : 1;
}

// ---------------- tf32 pre-rounding ----------------
__global__ void k_round_w(const float* __restrict__ W1, const float* __restrict__ W2,
                          const float* __restrict__ W3, const float* __restrict__ Wm1) {
    int i = blockIdx.x * blockDim.x + threadIdx.x;
    if (i >= WTOT) return;
    float v;
    if (i < W2OFF)       v = W1[i];
    else if (i < W3OFF)  v = W2[i - W2OFF];
    else if (i < WM1OFF) v = W3[i - W3OFF];
    else                 v = Wm1[i - WM1OFF];
    g_wr[i] = wmma::__float_to_tf32(v);
}

__global__ void k_round_x(const float* __restrict__ x, float* __restrict__ dst) {
    int i = blockIdx.x * blockDim.x + threadIdx.x;
    if (i >= NN * IN_FEAT) return;
    dst[i] = wmma::__float_to_tf32(x[i]);
}

// ---------------- GEMM v4: cp.async double-buffered tf32 -------------------
// 512 threads / 16 warps (4x4); warp tile 32x32 (2x2 frags); block 128x128;
// BK=32; inputs pre-rounded to tf32; direct fragment stores (C row-padded).
#define BGM 128
#define BGN 128
#define BGK 32
#define PA 36          // BGK + 4  (144B rows, 16B aligned)
#define PB 132         // BGN + 4  (528B rows, 16B aligned)
#define ASZ (BGM * PA) // floats per A stage
#define BSZ (BGK * PB)
#define G4_SMEM ((2 * ASZ + 2 * BSZ) * 4)   // 70656 bytes

__global__ __launch_bounds__(512) void k_gemm4(
    const float* __restrict__ A, const float* __restrict__ B,
    float* __restrict__ C, int M, int K)
{
    extern __shared__ float smem[];
    float* As = smem;                 // 2 stages
    float* Bs = smem + 2 * ASZ;

    int tid = threadIdx.x;
    int warp = tid >> 5;
    int wm = warp >> 2;          // 0..3
    int wn = warp & 3;           // 0..3
    int row0 = blockIdx.y * BGM;
    int col0 = blockIdx.x * BGN;

    wmma::fragment<wmma::accumulator, 16, 16, 8, float> acc[2][2];
#pragma unroll
    for (int i = 0; i < 2; i++)
#pragma unroll
        for (int j = 0; j < 2; j++) wmma::fill_fragment(acc[i][j], 0.0f);

    const int T = K / BGK;

    auto issue = [&](int t, int buf) {
        int k0 = t * BGK;
        float* Ab = As + buf * ASZ;
        float* Bb = Bs + buf * BSZ;
        // A tile 128x32 = 1024 float4; 2 per thread
#pragma unroll
        for (int i = 0; i < 2; i++) {
            int idx = tid + i * 512;
            int r = idx >> 3, c4 = (idx & 7) * 4;
            int gr = min(row0 + r, M - 1);          // clamp: pad rows get garbage, never read
            cp16(Ab + r * PA + c4, A + (size_t)gr * K + k0 + c4);
        }
        // B tile 32x128 = 1024 float4; 2 per thread (weights 256-wide, in-bounds)
#pragma unroll
        for (int i = 0; i < 2; i++) {
            int idx = tid + i * 512;
            int r = idx >> 5, c4 = (idx & 31) * 4;
            cp16(Bb + r * PB + c4, B + (size_t)(k0 + r) * HW + col0 + c4);
        }
        cp_commit();
    };

    issue(0, 0);

    for (int t = 0; t < T; t++) {
        int buf = t & 1;
        if (t + 1 < T) { issue(t + 1, (t + 1) & 1); cp_wait<1>(); }
        else           { cp_wait<0>(); }
        __syncthreads();

        float* Ab = As + buf * ASZ;
        float* Bb = Bs + buf * BSZ;
#pragma unroll
        for (int kk = 0; kk < BGK; kk += 8) {
            wmma::fragment<wmma::matrix_a, 16, 16, 8, wmma::precision::tf32, wmma::row_major> a[2];
            wmma::fragment<wmma::matrix_b, 16, 16, 8, wmma::precision::tf32, wmma::row_major> b[2];
            wmma::load_matrix_sync(a[0], Ab + (wm * 32 +  0) * PA + kk, PA);
            wmma::load_matrix_sync(a[1], Ab + (wm * 32 + 16) * PA + kk, PA);
            wmma::load_matrix_sync(b[0], Bb + kk * PB + wn * 32 +  0, PB);
            wmma::load_matrix_sync(b[1], Bb + kk * PB + wn * 32 + 16, PB);
#pragma unroll
            for (int i = 0; i < 2; i++)
#pragma unroll
                for (int j = 0; j < 2; j++)
                    wmma::mma_sync(acc[i][j], a[i], b[j], acc[i][j]);
        }
        __syncthreads();   // all warps done with buf before it is refilled
    }

#pragma unroll
    for (int i = 0; i < 2; i++)
#pragma unroll
        for (int j = 0; j < 2; j++) {
            int r = row0 + wm * 32 + i * 16;
            int c = col0 + wn * 32 + j * 16;
            wmma::store_matrix_sync(C + (size_t)r * HW + c, acc[i][j], HW,
                                    wmma::mem_row_major);
        }
}

// ---------------- CSR build ----------------
__global__ void k_zero_counts(int* counts, int n) {
    int i = blockIdx.x * blockDim.x + threadIdx.x;
    if (i < n) counts[i] = 0;
}

__global__ void k_build_edges(const void* __restrict__ ei,
                              int* __restrict__ src2, int* __restrict__ dst2,
                              int* __restrict__ counts) {
    int e = blockIdx.x * blockDim.x + threadIdx.x;
    if (e >= EE) return;
    int s, d;
    if (e < NE) {
        if (g_is64) {
            const long long* p = (const long long*)ei;
            s = (int)p[e]; d = (int)p[NE + e];
        } else {
            const int* p = (const int*)ei;
            s = p[e]; d = p[NE + e];
        }
        s = min(max(s, 0), NN - 1);
        d = min(max(d, 0), NN - 1);
    } else {
        s = d = e - NE;
    }
    src2[e] = s;
    dst2[e] = d;
    atomicAdd(&counts[d], 1);
}

#define SCAN_B 256
#define SCAN_NB ((NN + SCAN_B - 1) / SCAN_B)   // 196

__global__ void k_blocksum(const int* __restrict__ counts, int* __restrict__ bsum) {
    __shared__ int s[SCAN_B];
    int i = blockIdx.x * SCAN_B + threadIdx.x;
    s[threadIdx.x] = (i < NN) ? counts[i] : 0;
    __syncthreads();
    for (int off = 128; off > 0; off >>= 1) {
        if (threadIdx.x < off) s[threadIdx.x] += s[threadIdx.x + off];
        __syncthreads();
    }
    if (threadIdx.x == 0) bsum[blockIdx.x] = s[0];
}

__global__ void k_scan_top(int* __restrict__ bsum) {
    __shared__ int s[SCAN_B];
    int v = (threadIdx.x < SCAN_NB) ? bsum[threadIdx.x] : 0;
    s[threadIdx.x] = v;
    __syncthreads();
    for (int off = 1; off < SCAN_B; off <<= 1) {
        int t = (threadIdx.x >= off) ? s[threadIdx.x - off] : 0;
        __syncthreads();
        s[threadIdx.x] += t;
        __syncthreads();
    }
    if (threadIdx.x < SCAN_NB) bsum[threadIdx.x] = s[threadIdx.x] - v;
}

__global__ void k_scan_final(const int* __restrict__ counts, const int* __restrict__ bsum,
                             int* __restrict__ rowptr, int* __restrict__ fill) {
    __shared__ int s[SCAN_B];
    int i = blockIdx.x * SCAN_B + threadIdx.x;
    int v = (i < NN) ? counts[i] : 0;
    s[threadIdx.x] = v;
    __syncthreads();
    for (int off = 1; off < SCAN_B; off <<= 1) {
        int t = (threadIdx.x >= off) ? s[threadIdx.x - off] : 0;
        __syncthreads();
        s[threadIdx.x] += t;
        __syncthreads();
    }
    int excl = bsum[blockIdx.x] + s[threadIdx.x] - v;
    if (i < NN) { rowptr[i] = excl; fill[i] = excl; }
    if (i == NN - 1) rowptr[NN] = excl + v;
}

__global__ void k_scatter(const int* __restrict__ src2, const int* __restrict__ dst2,
                          int* __restrict__ fill, int* __restrict__ src_sorted) {
    int e = blockIdx.x * blockDim.x + threadIdx.x;
    if (e >= EE) return;
    int d = dst2[e];
    int p = atomicAdd(&fill[d], 1);
    src_sorted[p] = src2[e];
}

// ---------------- GEMM v1 (validated) for the N=40 head GEMM ----------------
#define GBM 128
#define GBN 64
#define GBK 16

__global__ __launch_bounds__(256) void k_gemm_tf32(
    const float* __restrict__ A, const float* __restrict__ B,
    float* __restrict__ C, int M, int N, int K,
    const float* __restrict__ bias, int do_relu)
{
    __shared__ float As[GBM][GBK + 4];
    __shared__ float Bs[GBK][GBN + 4];
    __shared__ float Cs[GBM][GBN];

    int tid = threadIdx.x;
    int warp = tid >> 5;
    int wm = warp >> 1;
    int wn = warp & 1;
    int row0 = blockIdx.y * GBM;
    int col0 = blockIdx.x * GBN;

    wmma::fragment<wmma::accumulator, 16, 16, 8, float> acc[2][2];
#pragma unroll
    for (int i = 0; i < 2; i++)
#pragma unroll
        for (int j = 0; j < 2; j++) wmma::fill_fragment(acc[i][j], 0.0f);

    for (int k0 = 0; k0 < K; k0 += GBK) {
#pragma unroll
        for (int t = 0; t < 2; t++) {
            int idx = tid + t * 256;
            int r = idx >> 2;
            int c4 = (idx & 3) * 4;
            float4 v = make_float4(0.f, 0.f, 0.f, 0.f);
            if (row0 + r < M)
                v = *(const float4*)(A + (size_t)(row0 + r) * K + k0 + c4);
            As[r][c4 + 0] = wmma::__float_to_tf32(v.x);
            As[r][c4 + 1] = wmma::__float_to_tf32(v.y);
            As[r][c4 + 2] = wmma::__float_to_tf32(v.z);
            As[r][c4 + 3] = wmma::__float_to_tf32(v.w);
        }
        {
            int r = tid >> 4;
            int c0 = (tid & 15) * 4;
#pragma unroll
            for (int j = 0; j < 4; j++) {
                int c = c0 + j;
                float v = 0.f;
                if (col0 + c < N) v = B[(size_t)(k0 + r) * N + col0 + c];
                Bs[r][c] = wmma::__float_to_tf32(v);
            }
        }
        __syncthreads();

#pragma unroll
        for (int kk = 0; kk < GBK; kk += 8) {
            wmma::fragment<wmma::matrix_a, 16, 16, 8, wmma::precision::tf32, wmma::row_major> a[2];
            wmma::fragment<wmma::matrix_b, 16, 16, 8, wmma::precision::tf32, wmma::row_major> b[2];
            wmma::load_matrix_sync(a[0], &As[wm * 32 +  0][kk], GBK + 4);
            wmma::load_matrix_sync(a[1], &As[wm * 32 + 16][kk], GBK + 4);
            wmma::load_matrix_sync(b[0], &Bs[kk][wn * 32 +  0], GBN + 4);
            wmma::load_matrix_sync(b[1], &Bs[kk][wn * 32 + 16], GBN + 4);
#pragma unroll
            for (int i = 0; i < 2; i++)
#pragma unroll
                for (int j = 0; j < 2; j++)
                    wmma::mma_sync(acc[i][j], a[i], b[j], acc[i][j]);
        }
        __syncthreads();
    }

#pragma unroll
    for (int i = 0; i < 2; i++)
#pragma unroll
        for (int j = 0; j < 2; j++)
            wmma::store_matrix_sync(&Cs[wm * 32 + i * 16][wn * 32 + j * 16],
                                    acc[i][j], GBN, wmma::mem_row_major);
    __syncthreads();

#pragma unroll
    for (int it = 0; it < 8; it++) {
        int idx = tid + it * 256;
        int r = idx >> 4;
        int c4 = (idx & 15) * 4;
        int gr = row0 + r;
        if (gr >= M) continue;
        float4 v = *(const float4*)&Cs[r][c4];
        int gc = col0 + c4;
        float* vv = &v.x;
        if (bias) {
#pragma unroll
            for (int j = 0; j < 4; j++)
                if (gc + j < N) vv[j] += bias[gc + j];
        }
        if (do_relu) {
#pragma unroll
            for (int j = 0; j < 4; j++) vv[j] = fmaxf(vv[j], 0.f);
        }
        if (gc + 4 <= N) {
            *(float4*)(C + (size_t)gr * N + gc) = v;
        } else {
#pragma unroll
            for (int j = 0; j < 4; j++)
                if (gc + j < N) C[(size_t)gr * N + gc + j] = vv[j];
        }
    }
}

// ---------------- bias+relu elementwise (for Wm1 epilogue) ------------------
__global__ void k_biasrelu(float* __restrict__ h, const float* __restrict__ bias) {
    int i = blockIdx.x * blockDim.x + threadIdx.x;     // over NN*64 float4
    if (i >= NN * 64) return;
    int c4 = (i & 63) * 4;
    float4 v = ((float4*)h)[i];
    const float4 b = *(const float4*)(bias + c4);
    v.x = fmaxf(v.x + b.x, 0.f); v.y = fmaxf(v.y + b.y, 0.f);
    v.z = fmaxf(v.z + b.z, 0.f); v.w = fmaxf(v.w + b.w, 0.f);
    ((float4*)h)[i] = v;
}

// ---------------- per-node attention logits: warp per node ------------------
__global__ void k_logits(const float* __restrict__ h, const float* __restrict__ a_s,
                         const float* __restrict__ a_d,
                         float* __restrict__ srcl, float* __restrict__ dstl) {
    int warp = (blockIdx.x * blockDim.x + threadIdx.x) >> 5;
    int lane = threadIdx.x & 31;
    if (warp >= NN) return;
    int n = warp;
    const float4* hp = (const float4*)(h + (size_t)n * HW) + lane * 2;
    float4 v0 = hp[0], v1 = hp[1];
    int head = lane >> 3, sub = lane & 7;
    const float4* ap = (const float4*)(a_s + head * 64 + sub * 8);
    const float4* dp = (const float4*)(a_d + head * 64 + sub * 8);
    float4 s0 = ap[0], s1 = ap[1];
    float4 d0 = dp[0], d1 = dp[1];
    float ps = v0.x * s0.x + v0.y * s0.y + v0.z * s0.z + v0.w * s0.w
             + v1.x * s1.x + v1.y * s1.y + v1.z * s1.z + v1.w * s1.w;
    float pd = v0.x * d0.x + v0.y * d0.y + v0.z * d0.z + v0.w * d0.w
             + v1.x * d1.x + v1.y * d1.y + v1.z * d1.z + v1.w * d1.w;
#pragma unroll
    for (int off = 4; off >= 1; off >>= 1) {
        ps += __shfl_down_sync(0xffffffffu, ps, off, 8);
        pd += __shfl_down_sync(0xffffffffu, pd, off, 8);
    }
    if (sub == 0) {
        srcl[n * 4 + head] = ps;
        dstl[n * 4 + head] = pd;
    }
}

// ---------------- segment max: one thread per (node, head) ------------------
__global__ void k_maxes(const float* __restrict__ srcl, const float* __restrict__ dstl,
                        const int* __restrict__ rowptr, const int* __restrict__ src_sorted,
                        float* __restrict__ amax) {
    int t = blockIdx.x * blockDim.x + threadIdx.x;
    if (t >= NN * 4) return;
    int n = t >> 2, hd = t & 3;
    float dl = dstl[t];
    int b = rowptr[n], e = rowptr[n + 1];
    float mx = -1e30f;
    for (int i = b; i < e; i++) {
        int s = src_sorted[i];
        float a = srcl[s * 4 + hd] + dl;
        a = a > 0.f ? a : 0.2f * a;       // leaky_relu(0.2)
        mx = fmaxf(mx, a);
    }
    amax[t] = mx;
}

// ---------------- fused softmax-aggregate: warp per node --------------------
// output rounded to tf32 (feeds next GEMM; numerically identical to
// converting inside the GEMM, which is what the validated kernels did).
__global__ void k_agg_fused(const float* __restrict__ h, const int* __restrict__ rowptr,
                            const int* __restrict__ src_sorted,
                            const float* __restrict__ srcl, const float* __restrict__ dstl,
                            const float* __restrict__ amax, const float* __restrict__ bias,
                            float* __restrict__ out) {
    int warp = (blockIdx.x * blockDim.x + threadIdx.x) >> 5;
    int lane = threadIdx.x & 31;
    if (warp >= NN) return;
    int n = warp;
    int head = lane >> 3;
    float am = amax[n * 4 + head];
    float dl = dstl[n * 4 + head];
    int b = rowptr[n], e = rowptr[n + 1];
    float den = 0.f;
    float4 a0 = make_float4(0.f, 0.f, 0.f, 0.f);
    float4 a1 = make_float4(0.f, 0.f, 0.f, 0.f);
    for (int i = b; i < e; i++) {
        int s = src_sorted[i];
        float a = __ldg(&srcl[s * 4 + head]) + dl;
        a = a > 0.f ? a : 0.2f * a;
        float ev = __expf(a - am);
        den += ev;
        const float4* hp = (const float4*)(h + (size_t)s * HW) + lane * 2;
        float4 v0 = hp[0], v1 = hp[1];
        a0.x += v0.x * ev; a0.y += v0.y * ev; a0.z += v0.z * ev; a0.w += v0.w * ev;
        a1.x += v1.x * ev; a1.y += v1.y * ev; a1.z += v1.z * ev; a1.w += v1.w * ev;
    }
    float rinv = 1.0f / den;
    const float4* bp = (const float4*)bias + lane * 2;
    float4 b0 = bp[0], b1 = bp[1];
    float4 o0, o1;
    o0.x = wmma::__float_to_tf32(fmaxf(a0.x * rinv + b0.x, 0.f));
    o0.y = wmma::__float_to_tf32(fmaxf(a0.y * rinv + b0.y, 0.f));
    o0.z = wmma::__float_to_tf32(fmaxf(a0.z * rinv + b0.z, 0.f));
    o0.w = wmma::__float_to_tf32(fmaxf(a0.w * rinv + b0.w, 0.f));
    o1.x = wmma::__float_to_tf32(fmaxf(a1.x * rinv + b1.x, 0.f));
    o1.y = wmma::__float_to_tf32(fmaxf(a1.y * rinv + b1.y, 0.f));
    o1.z = wmma::__float_to_tf32(fmaxf(a1.z * rinv + b1.z, 0.f));
    o1.w = wmma::__float_to_tf32(fmaxf(a1.w * rinv + b1.w, 0.f));
    float4* op = (float4*)(out + (size_t)n * HW) + lane * 2;
    op[0] = o0; op[1] = o1;
}

// ---------------- host launcher ----------------
extern "C" void kernel_launch(void* const* d_in, const int* in_sizes, int n_in,
                              void* d_out, int out_size) {
    const float* x   = (const float*)d_in[0];
    const void*  ei  = d_in[1];
    const float* W1  = (const float*)d_in[2];
    const float* as1 = (const float*)d_in[3];
    const float* ad1 = (const float*)d_in[4];
    const float* b1  = (const float*)d_in[5];
    const float* W2  = (const float*)d_in[6];
    const float* as2 = (const float*)d_in[7];
    const float* ad2 = (const float*)d_in[8];
    const float* b2  = (const float*)d_in[9];
    const float* W3  = (const float*)d_in[10];
    const float* as3 = (const float*)d_in[11];
    const float* ad3 = (const float*)d_in[12];
    const float* b3  = (const float*)d_in[13];
    const float* Wm1 = (const float*)d_in[14];
    const float* bm1 = (const float*)d_in[15];
    const float* Wm2 = (const float*)d_in[16];
    const float* bm2 = (const float*)d_in[17];
    float* out = (float*)d_out;

    float *p_h, *p_feat, *p_wr, *p_srcl, *p_dstl, *p_amax;
    int *p_src2, *p_dst2, *p_srcs, *p_counts, *p_fill, *p_rowptr, *p_bsum;
    cudaGetSymbolAddress((void**)&p_h, g_h);
    cudaGetSymbolAddress((void**)&p_feat, g_feat);
    cudaGetSymbolAddress((void**)&p_wr, g_wr);
    cudaGetSymbolAddress((void**)&p_srcl, g_srcl);
    cudaGetSymbolAddress((void**)&p_dstl, g_dstl);
    cudaGetSymbolAddress((void**)&p_amax, g_amax);
    cudaGetSymbolAddress((void**)&p_src2, g_src2);
    cudaGetSymbolAddress((void**)&p_dst2, g_dst2);
    cudaGetSymbolAddress((void**)&p_srcs, g_src_sorted);
    cudaGetSymbolAddress((void**)&p_counts, g_counts);
    cudaGetSymbolAddress((void**)&p_fill, g_fill);
    cudaGetSymbolAddress((void**)&p_rowptr, g_rowptr);
    cudaGetSymbolAddress((void**)&p_bsum, g_bsum);

    cudaFuncSetAttribute(k_gemm4, cudaFuncAttributeMaxDynamicSharedMemorySize, G4_SMEM);

    const int warpsGrid = (NN * 32 + 255) / 256;
    const int maxGrid   = (NN * 4 + 255) / 256;
    dim3 bigGrid(HW / BGN, NNP / BGM);                   // (2, 391)
    dim3 outGrid(1, (NN + GBM - 1) / GBM);               // (1, 391)

    // slots 0..3: detect, round_w, round_x, GEMM1 (slot 3 = ncu capture window)
    k_detect<<<1, 512>>>(ei);                                              // 0
    k_round_w<<<(WTOT + 255) / 256, 256>>>(W1, W2, W3, Wm1);               // 1
    k_round_x<<<(NN * IN_FEAT + 255) / 256, 256>>>(x, p_feat);             // 2
    k_gemm4<<<bigGrid, 512, G4_SMEM>>>(p_feat, p_wr + W1OFF, p_h, NN, IN_FEAT); // 3

    // CSR build (independent of GEMM1)
    k_zero_counts<<<(NN + 255) / 256, 256>>>(p_counts, NN);
    k_build_edges<<<(EE + 255) / 256, 256>>>(ei, p_src2, p_dst2, p_counts);
    k_blocksum<<<SCAN_NB, SCAN_B>>>(p_counts, p_bsum);
    k_scan_top<<<1, SCAN_B>>>(p_bsum);
    k_scan_final<<<SCAN_NB, SCAN_B>>>(p_counts, p_bsum, p_rowptr, p_fill);
    k_scatter<<<(EE + 255) / 256, 256>>>(p_src2, p_dst2, p_fill, p_srcs);

    // --- GAT layer 1 rest ---
    k_logits<<<warpsGrid, 256>>>(p_h, as1, ad1, p_srcl, p_dstl);
    k_maxes<<<maxGrid, 256>>>(p_srcl, p_dstl, p_rowptr, p_srcs, p_amax);
    k_agg_fused<<<warpsGrid, 256>>>(p_h, p_rowptr, p_srcs, p_srcl, p_dstl, p_amax, b1, p_feat);

    // --- GAT layer 2 ---
    k_gemm4<<<bigGrid, 512, G4_SMEM>>>(p_feat, p_wr + W2OFF, p_h, NN, HW);
    k_logits<<<warpsGrid, 256>>>(p_h, as2, ad2, p_srcl, p_dstl);
    k_maxes<<<maxGrid, 256>>>(p_srcl, p_dstl, p_rowptr, p_srcs, p_amax);
    k_agg_fused<<<warpsGrid, 256>>>(p_h, p_rowptr, p_srcs, p_srcl, p_dstl, p_amax, b2, p_feat);

    // --- GAT layer 3 ---
    k_gemm4<<<bigGrid, 512, G4_SMEM>>>(p_feat, p_wr + W3OFF, p_h, NN, HW);
    k_logits<<<warpsGrid, 256>>>(p_h, as3, ad3, p_srcl, p_dstl);
    k_maxes<<<maxGrid, 256>>>(p_srcl, p_dstl, p_rowptr, p_srcs, p_amax);
    k_agg_fused<<<warpsGrid, 256>>>(p_h, p_rowptr, p_srcs, p_srcl, p_dstl, p_amax, b3, p_feat);

    // --- MLP head ---
    k_gemm4<<<bigGrid, 512, G4_SMEM>>>(p_feat, p_wr + WM1OFF, p_h, NN, HW);
    k_biasrelu<<<(NN * 64 + 255) / 256, 256>>>(p_h, bm1);
    k_gemm_tf32<<<outGrid, 256>>>(p_h, Wm2, out, NN, OUTF, HW, bm2, 0);
}

// round 14
// speedup vs baseline: 1.8857x; 1.0837x over previous
#include <cuda_runtime.h>
#include <cuda_bf16.h>
#include <mma.h>
#include <cstdint>

using namespace nvcuda;

#define NN 50000
#define NNP 50048              // 391*128: padded rows for guard-free direct GEMM stores
#define NE 800000
#define EE (NE + NN)           // edges + self loops = 850000
#define HW 256
#define IN_FEAT 128
#define OUTF 40

// weight scratch offsets (tf32-rounded copies)
#define W1OFF 0
#define W2OFF 32768
#define W3OFF 98304
#define WM1OFF 163840
#define WTOT 229376

// ---------------- scratch ----------------
__device__ float g_h[NNP * HW];
__device__ float g_feat[NN * HW];
__device__ float g_wr[WTOT];
__device__ float g_srcl[NN * 4];
__device__ float g_dstl[NN * 4];
__device__ float g_amax[NN * 4];
__device__ int   g_src2[EE];
__device__ int   g_dst2[EE];
__device__ int   g_src_sorted[EE];
__device__ int   g_counts[NN];
__device__ int   g_fill[NN];
__device__ int   g_rowptr[NN + 1];
__device__ int   g_bsum[256];
__device__ int   g_is64;

// ---------------- cp.async helpers ----------------
__device__ __forceinline__ void cp16(void* dst_smem, const void* src) {
    uint32_t sa = (uint32_t)__cvta_generic_to_shared(dst_smem);
    asm volatile("cp.async.ca.shared.global [%0], [%1], 16;\n" :: "r"(sa), "l"(src));
}
__device__ __forceinline__ void cp_commit() {
    asm volatile("cp.async.commit_group;\n");
}
template <int N>
__device__ __forceinline__ void cp_wait() {
    asm volatile("cp.async.wait_group %0;\n" :: "n"(N));
}

// ---------------- dtype detection ----------------
__global__ void k_detect(const void* __restrict__ ei) {
    __shared__ int bad;
    if (threadIdx.x == 0) bad = 0;
    __syncthreads();
    const long long* p = (const long long*)ei;
    long long v = p[threadIdx.x];
    if (v < 0 || v >= (long long)NN) bad = 1;
    __syncthreads();
    if (threadIdx.x == 0) g_is64 = bad ? 0 : 1;
}

// ---------------- tf32 pre-rounding ----------------
__global__ void k_round_w(const float* __restrict__ W1, const float* __restrict__ W2,
                          const float* __restrict__ W3, const float* __restrict__ Wm1) {
    int i = blockIdx.x * blockDim.x + threadIdx.x;
    if (i >= WTOT) return;
    float v;
    if (i < W2OFF)       v = W1[i];
    else if (i < W3OFF)  v = W2[i - W2OFF];
    else if (i < WM1OFF) v = W3[i - W3OFF];
    else                 v = Wm1[i - WM1OFF];
    g_wr[i] = wmma::__float_to_tf32(v);
}

__global__ void k_round_x(const float* __restrict__ x, float* __restrict__ dst) {
    int i = blockIdx.x * blockDim.x + threadIdx.x;
    if (i >= NN * IN_FEAT) return;
    dst[i] = wmma::__float_to_tf32(x[i]);
}

// ---------------- GEMM v5: 256thr / 8 warps, warp tile 64x32 (4x2 frags) ---
// block 128x128, BK=32, 2-stage cp.async; inputs pre-rounded tf32;
// direct fragment stores (C row-padded, ldc=256).
#define BGM 128
#define BGN 128
#define BGK 32
#define PA 36
#define PB 132
#define ASZ (BGM * PA)
#define BSZ (BGK * PB)
#define G4_SMEM ((2 * ASZ + 2 * BSZ) * 4)   // 70656 bytes

__global__ __launch_bounds__(256, 2) void k_gemm4(
    const float* __restrict__ A, const float* __restrict__ B,
    float* __restrict__ C, int M, int K)
{
    extern __shared__ float smem[];
    float* As = smem;
    float* Bs = smem + 2 * ASZ;

    int tid = threadIdx.x;
    int warp = tid >> 5;
    int wm = warp >> 2;          // 0..1 -> 64-row slab
    int wn = warp & 3;           // 0..3 -> 32-col slab
    int row0 = blockIdx.y * BGM;
    int col0 = blockIdx.x * BGN;

    wmma::fragment<wmma::accumulator, 16, 16, 8, float> acc[4][2];
#pragma unroll
    for (int i = 0; i < 4; i++)
#pragma unroll
        for (int j = 0; j < 2; j++) wmma::fill_fragment(acc[i][j], 0.0f);

    const int T = K / BGK;

    auto issue = [&](int t, int buf) {
        int k0 = t * BGK;
        float* Ab = As + buf * ASZ;
        float* Bb = Bs + buf * BSZ;
        // A tile 128x32 = 1024 float4; 4 per thread
#pragma unroll
        for (int i = 0; i < 4; i++) {
            int idx = tid + i * 256;
            int r = idx >> 3, c4 = (idx & 7) * 4;
            int gr = min(row0 + r, M - 1);          // clamp: pad rows never read
            cp16(Ab + r * PA + c4, A + (size_t)gr * K + k0 + c4);
        }
        // B tile 32x128 = 1024 float4; 4 per thread
#pragma unroll
        for (int i = 0; i < 4; i++) {
            int idx = tid + i * 256;
            int r = idx >> 5, c4 = (idx & 31) * 4;
            cp16(Bb + r * PB + c4, B + (size_t)(k0 + r) * HW + col0 + c4);
        }
        cp_commit();
    };

    issue(0, 0);

    for (int t = 0; t < T; t++) {
        int buf = t & 1;
        if (t + 1 < T) { issue(t + 1, (t + 1) & 1); cp_wait<1>(); }
        else           { cp_wait<0>(); }
        __syncthreads();

        float* Ab = As + buf * ASZ;
        float* Bb = Bs + buf * BSZ;
#pragma unroll
        for (int kk = 0; kk < BGK; kk += 8) {
            wmma::fragment<wmma::matrix_a, 16, 16, 8, wmma::precision::tf32, wmma::row_major> a[4];
            wmma::fragment<wmma::matrix_b, 16, 16, 8, wmma::precision::tf32, wmma::row_major> b[2];
#pragma unroll
            for (int i = 0; i < 4; i++)
                wmma::load_matrix_sync(a[i], Ab + (wm * 64 + i * 16) * PA + kk, PA);
#pragma unroll
            for (int j = 0; j < 2; j++)
                wmma::load_matrix_sync(b[j], Bb + kk * PB + wn * 32 + j * 16, PB);
#pragma unroll
            for (int i = 0; i < 4; i++)
#pragma unroll
                for (int j = 0; j < 2; j++)
                    wmma::mma_sync(acc[i][j], a[i], b[j], acc[i][j]);
        }
        __syncthreads();
    }

#pragma unroll
    for (int i = 0; i < 4; i++)
#pragma unroll
        for (int j = 0; j < 2; j++) {
            int r = row0 + wm * 64 + i * 16;
            int c = col0 + wn * 32 + j * 16;
            wmma::store_matrix_sync(C + (size_t)r * HW + c, acc[i][j], HW,
                                    wmma::mem_row_major);
        }
}

// ---------------- CSR build ----------------
__global__ void k_zero_counts(int* counts, int n) {
    int i = blockIdx.x * blockDim.x + threadIdx.x;
    if (i < n) counts[i] = 0;
}

__global__ void k_build_edges(const void* __restrict__ ei,
                              int* __restrict__ src2, int* __restrict__ dst2,
                              int* __restrict__ counts) {
    int e = blockIdx.x * blockDim.x + threadIdx.x;
    if (e >= EE) return;
    int s, d;
    if (e < NE) {
        if (g_is64) {
            const long long* p = (const long long*)ei;
            s = (int)p[e]; d = (int)p[NE + e];
        } else {
            const int* p = (const int*)ei;
            s = p[e]; d = p[NE + e];
        }
        s = min(max(s, 0), NN - 1);
        d = min(max(d, 0), NN - 1);
    } else {
        s = d = e - NE;
    }
    src2[e] = s;
    dst2[e] = d;
    atomicAdd(&counts[d], 1);
}

#define SCAN_B 256
#define SCAN_NB ((NN + SCAN_B - 1) / SCAN_B)   // 196

__global__ void k_blocksum(const int* __restrict__ counts, int* __restrict__ bsum) {
    __shared__ int s[SCAN_B];
    int i = blockIdx.x * SCAN_B + threadIdx.x;
    s[threadIdx.x] = (i < NN) ? counts[i] : 0;
    __syncthreads();
    for (int off = 128; off > 0; off >>= 1) {
        if (threadIdx.x < off) s[threadIdx.x] += s[threadIdx.x + off];
        __syncthreads();
    }
    if (threadIdx.x == 0) bsum[blockIdx.x] = s[0];
}

__global__ void k_scan_top(int* __restrict__ bsum) {
    __shared__ int s[SCAN_B];
    int v = (threadIdx.x < SCAN_NB) ? bsum[threadIdx.x] : 0;
    s[threadIdx.x] = v;
    __syncthreads();
    for (int off = 1; off < SCAN_B; off <<= 1) {
        int t = (threadIdx.x >= off) ? s[threadIdx.x - off] : 0;
        __syncthreads();
        s[threadIdx.x] += t;
        __syncthreads();
    }
    if (threadIdx.x < SCAN_NB) bsum[threadIdx.x] = s[threadIdx.x] - v;
}

__global__ void k_scan_final(const int* __restrict__ counts, const int* __restrict__ bsum,
                             int* __restrict__ rowptr, int* __restrict__ fill) {
    __shared__ int s[SCAN_B];
    int i = blockIdx.x * SCAN_B + threadIdx.x;
    int v = (i < NN) ? counts[i] : 0;
    s[threadIdx.x] = v;
    __syncthreads();
    for (int off = 1; off < SCAN_B; off <<= 1) {
        int t = (threadIdx.x >= off) ? s[threadIdx.x - off] : 0;
        __syncthreads();
        s[threadIdx.x] += t;
        __syncthreads();
    }
    int excl = bsum[blockIdx.x] + s[threadIdx.x] - v;
    if (i < NN) { rowptr[i] = excl; fill[i] = excl; }
    if (i == NN - 1) rowptr[NN] = excl + v;
}

__global__ void k_scatter(const int* __restrict__ src2, const int* __restrict__ dst2,
                          int* __restrict__ fill, int* __restrict__ src_sorted) {
    int e = blockIdx.x * blockDim.x + threadIdx.x;
    if (e >= EE) return;
    int d = dst2[e];
    int p = atomicAdd(&fill[d], 1);
    src_sorted[p] = src2[e];
}

// ---------------- GEMM v1 (validated) for the N=40 head GEMM ----------------
#define GBM 128
#define GBN 64
#define GBK 16

__global__ __launch_bounds__(256) void k_gemm_tf32(
    const float* __restrict__ A, const float* __restrict__ B,
    float* __restrict__ C, int M, int N, int K,
    const float* __restrict__ bias, int do_relu)
{
    __shared__ float As[GBM][GBK + 4];
    __shared__ float Bs[GBK][GBN + 4];
    __shared__ float Cs[GBM][GBN];

    int tid = threadIdx.x;
    int warp = tid >> 5;
    int wm = warp >> 1;
    int wn = warp & 1;
    int row0 = blockIdx.y * GBM;
    int col0 = blockIdx.x * GBN;

    wmma::fragment<wmma::accumulator, 16, 16, 8, float> acc[2][2];
#pragma unroll
    for (int i = 0; i < 2; i++)
#pragma unroll
        for (int j = 0; j < 2; j++) wmma::fill_fragment(acc[i][j], 0.0f);

    for (int k0 = 0; k0 < K; k0 += GBK) {
#pragma unroll
        for (int t = 0; t < 2; t++) {
            int idx = tid + t * 256;
            int r = idx >> 2;
            int c4 = (idx & 3) * 4;
            float4 v = make_float4(0.f, 0.f, 0.f, 0.f);
            if (row0 + r < M)
                v = *(const float4*)(A + (size_t)(row0 + r) * K + k0 + c4);
            As[r][c4 + 0] = wmma::__float_to_tf32(v.x);
            As[r][c4 + 1] = wmma::__float_to_tf32(v.y);
            As[r][c4 + 2] = wmma::__float_to_tf32(v.z);
            As[r][c4 + 3] = wmma::__float_to_tf32(v.w);
        }
        {
            int r = tid >> 4;
            int c0 = (tid & 15) * 4;
#pragma unroll
            for (int j = 0; j < 4; j++) {
                int c = c0 + j;
                float v = 0.f;
                if (col0 + c < N) v = B[(size_t)(k0 + r) * N + col0 + c];
                Bs[r][c] = wmma::__float_to_tf32(v);
            }
        }
        __syncthreads();

#pragma unroll
        for (int kk = 0; kk < GBK; kk += 8) {
            wmma::fragment<wmma::matrix_a, 16, 16, 8, wmma::precision::tf32, wmma::row_major> a[2];
            wmma::fragment<wmma::matrix_b, 16, 16, 8, wmma::precision::tf32, wmma::row_major> b[2];
            wmma::load_matrix_sync(a[0], &As[wm * 32 +  0][kk], GBK + 4);
            wmma::load_matrix_sync(a[1], &As[wm * 32 + 16][kk], GBK + 4);
            wmma::load_matrix_sync(b[0], &Bs[kk][wn * 32 +  0], GBN + 4);
            wmma::load_matrix_sync(b[1], &Bs[kk][wn * 32 + 16], GBN + 4);
#pragma unroll
            for (int i = 0; i < 2; i++)
#pragma unroll
                for (int j = 0; j < 2; j++)
                    wmma::mma_sync(acc[i][j], a[i], b[j], acc[i][j]);
        }
        __syncthreads();
    }

#pragma unroll
    for (int i = 0; i < 2; i++)
#pragma unroll
        for (int j = 0; j < 2; j++)
            wmma::store_matrix_sync(&Cs[wm * 32 + i * 16][wn * 32 + j * 16],
                                    acc[i][j], GBN, wmma::mem_row_major);
    __syncthreads();

#pragma unroll
    for (int it = 0; it < 8; it++) {
        int idx = tid + it * 256;
        int r = idx >> 4;
        int c4 = (idx & 15) * 4;
        int gr = row0 + r;
        if (gr >= M) continue;
        float4 v = *(const float4*)&Cs[r][c4];
        int gc = col0 + c4;
        float* vv = &v.x;
        if (bias) {
#pragma unroll
            for (int j = 0; j < 4; j++)
                if (gc + j < N) vv[j] += bias[gc + j];
        }
        if (do_relu) {
#pragma unroll
            for (int j = 0; j < 4; j++) vv[j] = fmaxf(vv[j], 0.f);
        }
        if (gc + 4 <= N) {
            *(float4*)(C + (size_t)gr * N + gc) = v;
        } else {
#pragma unroll
            for (int j = 0; j < 4; j++)
                if (gc + j < N) C[(size_t)gr * N + gc + j] = vv[j];
        }
    }
}

// ---------------- bias+relu elementwise (for Wm1 epilogue) ------------------
__global__ void k_biasrelu(float* __restrict__ h, const float* __restrict__ bias) {
    int i = blockIdx.x * blockDim.x + threadIdx.x;     // over NN*64 float4
    if (i >= NN * 64) return;
    int c4 = (i & 63) * 4;
    float4 v = ((float4*)h)[i];
    const float4 b = *(const float4*)(bias + c4);
    v.x = fmaxf(v.x + b.x, 0.f); v.y = fmaxf(v.y + b.y, 0.f);
    v.z = fmaxf(v.z + b.z, 0.f); v.w = fmaxf(v.w + b.w, 0.f);
    ((float4*)h)[i] = v;
}

// ---------------- per-node attention logits: warp per node ------------------
__global__ void k_logits(const float* __restrict__ h, const float* __restrict__ a_s,
                         const float* __restrict__ a_d,
                         float* __restrict__ srcl, float* __restrict__ dstl) {
    int warp = (blockIdx.x * blockDim.x + threadIdx.x) >> 5;
    int lane = threadIdx.x & 31;
    if (warp >= NN) return;
    int n = warp;
    const float4* hp = (const float4*)(h + (size_t)n * HW) + lane * 2;
    float4 v0 = hp[0], v1 = hp[1];
    int head = lane >> 3, sub = lane & 7;
    const float4* ap = (const float4*)(a_s + head * 64 + sub * 8);
    const float4* dp = (const float4*)(a_d + head * 64 + sub * 8);
    float4 s0 = ap[0], s1 = ap[1];
    float4 d0 = dp[0], d1 = dp[1];
    float ps = v0.x * s0.x + v0.y * s0.y + v0.z * s0.z + v0.w * s0.w
             + v1.x * s1.x + v1.y * s1.y + v1.z * s1.z + v1.w * s1.w;
    float pd = v0.x * d0.x + v0.y * d0.y + v0.z * d0.z + v0.w * d0.w
             + v1.x * d1.x + v1.y * d1.y + v1.z * d1.z + v1.w * d1.w;
#pragma unroll
    for (int off = 4; off >= 1; off >>= 1) {
        ps += __shfl_down_sync(0xffffffffu, ps, off, 8);
        pd += __shfl_down_sync(0xffffffffu, pd, off, 8);
    }
    if (sub == 0) {
        srcl[n * 4 + head] = ps;
        dstl[n * 4 + head] = pd;
    }
}

// ---------------- segment max: one thread per (node, head) ------------------
__global__ void k_maxes(const float* __restrict__ srcl, const float* __restrict__ dstl,
                        const int* __restrict__ rowptr, const int* __restrict__ src_sorted,
                        float* __restrict__ amax) {
    int t = blockIdx.x * blockDim.x + threadIdx.x;
    if (t >= NN * 4) return;
    int n = t >> 2, hd = t & 3;
    float dl = dstl[t];
    int b = rowptr[n], e = rowptr[n + 1];
    float mx = -1e30f;
    for (int i = b; i < e; i++) {
        int s = src_sorted[i];
        float a = srcl[s * 4 + hd] + dl;
        a = a > 0.f ? a : 0.2f * a;       // leaky_relu(0.2)
        mx = fmaxf(mx, a);
    }
    amax[t] = mx;
}

// ---------------- fused softmax-aggregate: warp per node --------------------
__global__ void k_agg_fused(const float* __restrict__ h, const int* __restrict__ rowptr,
                            const int* __restrict__ src_sorted,
                            const float* __restrict__ srcl, const float* __restrict__ dstl,
                            const float* __restrict__ amax, const float* __restrict__ bias,
                            float* __restrict__ out) {
    int warp = (blockIdx.x * blockDim.x + threadIdx.x) >> 5;
    int lane = threadIdx.x & 31;
    if (warp >= NN) return;
    int n = warp;
    int head = lane >> 3;
    float am = amax[n * 4 + head];
    float dl = dstl[n * 4 + head];
    int b = rowptr[n], e = rowptr[n + 1];
    float den = 0.f;
    float4 a0 = make_float4(0.f, 0.f, 0.f, 0.f);
    float4 a1 = make_float4(0.f, 0.f, 0.f, 0.f);
    for (int i = b; i < e; i++) {
        int s = src_sorted[i];
        float a = __ldg(&srcl[s * 4 + head]) + dl;
        a = a > 0.f ? a : 0.2f * a;
        float ev = __expf(a - am);
        den += ev;
        const float4* hp = (const float4*)(h + (size_t)s * HW) + lane * 2;
        float4 v0 = hp[0], v1 = hp[1];
        a0.x += v0.x * ev; a0.y += v0.y * ev; a0.z += v0.z * ev; a0.w += v0.w * ev;
        a1.x += v1.x * ev; a1.y += v1.y * ev; a1.z += v1.z * ev; a1.w += v1.w * ev;
    }
    float rinv = 1.0f / den;
    const float4* bp = (const float4*)bias + lane * 2;
    float4 b0 = bp[0], b1 = bp[1];
    float4 o0, o1;
    o0.x = wmma::__float_to_tf32(fmaxf(a0.x * rinv + b0.x, 0.f));
    o0.y = wmma::__float_to_tf32(fmaxf(a0.y * rinv + b0.y, 0.f));
    o0.z = wmma::__float_to_tf32(fmaxf(a0.z * rinv + b0.z, 0.f));
    o0.w = wmma::__float_to_tf32(fmaxf(a0.w * rinv + b0.w, 0.f));
    o1.x = wmma::__float_to_tf32(fmaxf(a1.x * rinv + b1.x, 0.f));
    o1.y = wmma::__float_to_tf32(fmaxf(a1.y * rinv + b1.y, 0.f));
    o1.z = wmma::__float_to_tf32(fmaxf(a1.z * rinv + b1.z, 0.f));
    o1.w = wmma::__float_to_tf32(fmaxf(a1.w * rinv + b1.w, 0.f));
    float4* op = (float4*)(out + (size_t)n * HW) + lane * 2;
    op[0] = o0; op[1] = o1;
}

// ---------------- host launcher ----------------
extern "C" void kernel_launch(void* const* d_in, const int* in_sizes, int n_in,
                              void* d_out, int out_size) {
    const float* x   = (const float*)d_in[0];
    const void*  ei  = d_in[1];
    const float* W1  = (const float*)d_in[2];
    const float* as1 = (const float*)d_in[3];
    const float* ad1 = (const float*)d_in[4];
    const float* b1  = (const float*)d_in[5];
    const float* W2  = (const float*)d_in[6];
    const float* as2 = (const float*)d_in[7];
    const float* ad2 = (const float*)d_in[8];
    const float* b2  = (const float*)d_in[9];
    const float* W3  = (const float*)d_in[10];
    const float* as3 = (const float*)d_in[11];
    const float* ad3 = (const float*)d_in[12];
    const float* b3  = (const float*)d_in[13];
    const float* Wm1 = (const float*)d_in[14];
    const float* bm1 = (const float*)d_in[15];
    const float* Wm2 = (const float*)d_in[16];
    const float* bm2 = (const float*)d_in[17];
    float* out = (float*)d_out;

    float *p_h, *p_feat, *p_wr, *p_srcl, *p_dstl, *p_amax;
    int *p_src2, *p_dst2, *p_srcs, *p_counts, *p_fill, *p_rowptr, *p_bsum;
    cudaGetSymbolAddress((void**)&p_h, g_h);
    cudaGetSymbolAddress((void**)&p_feat, g_feat);
    cudaGetSymbolAddress((void**)&p_wr, g_wr);
    cudaGetSymbolAddress((void**)&p_srcl, g_srcl);
    cudaGetSymbolAddress((void**)&p_dstl, g_dstl);
    cudaGetSymbolAddress((void**)&p_amax, g_amax);
    cudaGetSymbolAddress((void**)&p_src2, g_src2);
    cudaGetSymbolAddress((void**)&p_dst2, g_dst2);
    cudaGetSymbolAddress((void**)&p_srcs, g_src_sorted);
    cudaGetSymbolAddress((void**)&p_counts, g_counts);
    cudaGetSymbolAddress((void**)&p_fill, g_fill);
    cudaGetSymbolAddress((void**)&p_rowptr, g_rowptr);
    cudaGetSymbolAddress((void**)&p_bsum, g_bsum);

    cudaFuncSetAttribute(k_gemm4, cudaFuncAttributeMaxDynamicSharedMemorySize, G4_SMEM);

    const int warpsGrid = (NN * 32 + 255) / 256;
    const int maxGrid   = (NN * 4 + 255) / 256;
    dim3 bigGrid(HW / BGN, NNP / BGM);                   // (2, 391)
    dim3 outGrid(1, (NN + GBM - 1) / GBM);               // (1, 391)

    // slots 0..3: detect, round_w, round_x, GEMM1 (slot 3 = ncu capture window)
    k_detect<<<1, 512>>>(ei);                                              // 0
    k_round_w<<<(WTOT + 255) / 256, 256>>>(W1, W2, W3, Wm1);               // 1
    k_round_x<<<(NN * IN_FEAT + 255) / 256, 256>>>(x, p_feat);             // 2
    k_gemm4<<<bigGrid, 256, G4_SMEM>>>(p_feat, p_wr + W1OFF, p_h, NN, IN_FEAT); // 3

    // CSR build (independent of GEMM1)
    k_zero_counts<<<(NN + 255) / 256, 256>>>(p_counts, NN);
    k_build_edges<<<(EE + 255) / 256, 256>>>(ei, p_src2, p_dst2, p_counts);
    k_blocksum<<<SCAN_NB, SCAN_B>>>(p_counts, p_bsum);
    k_scan_top<<<1, SCAN_B>>>(p_bsum);
    k_scan_final<<<SCAN_NB, SCAN_B>>>(p_counts, p_bsum, p_rowptr, p_fill);
    k_scatter<<<(EE + 255) / 256, 256>>>(p_src2, p_dst2, p_fill, p_srcs);

    // --- GAT layer 1 rest ---
    k_logits<<<warpsGrid, 256>>>(p_h, as1, ad1, p_srcl, p_dstl);
    k_maxes<<<maxGrid, 256>>>(p_srcl, p_dstl, p_rowptr, p_srcs, p_amax);
    k_agg_fused<<<warpsGrid, 256>>>(p_h, p_rowptr, p_srcs, p_srcl, p_dstl, p_amax, b1, p_feat);

    // --- GAT layer 2 ---
    k_gemm4<<<bigGrid, 256, G4_SMEM>>>(p_feat, p_wr + W2OFF, p_h, NN, HW);
    k_logits<<<warpsGrid, 256>>>(p_h, as2, ad2, p_srcl, p_dstl);
    k_maxes<<<maxGrid, 256>>>(p_srcl, p_dstl, p_rowptr, p_srcs, p_amax);
    k_agg_fused<<<warpsGrid, 256>>>(p_h, p_rowptr, p_srcs, p_srcl, p_dstl, p_amax, b2, p_feat);

    // --- GAT layer 3 ---
    k_gemm4<<<bigGrid, 256, G4_SMEM>>>(p_feat, p_wr + W3OFF, p_h, NN, HW);
    k_logits<<<warpsGrid, 256>>>(p_h, as3, ad3, p_srcl, p_dstl);
    k_maxes<<<maxGrid, 256>>>(p_srcl, p_dstl, p_rowptr, p_srcs, p_amax);
    k_agg_fused<<<warpsGrid, 256>>>(p_h, p_rowptr, p_srcs, p_srcl, p_dstl, p_amax, b3, p_feat);

    // --- MLP head ---
    k_gemm4<<<bigGrid, 256, G4_SMEM>>>(p_feat, p_wr + WM1OFF, p_h, NN, HW);
    k_biasrelu<<<(NN * 64 + 255) / 256, 256>>>(p_h, bm1);
    k_gemm_tf32<<<outGrid, 256>>>(p_h, Wm2, out, NN, OUTF, HW, bm2, 0);
}